// round 9
// baseline (speedup 1.0000x reference)
#include <cuda_runtime.h>
#include <cuda_bf16.h>
#include <stdint.h>
#include <math.h>

#define NBt 256
#define POS 676          // 26*26
#define LLt 624
#define DDc 128
#define CHc 256
#define HP  28           // padded grid 28x28
#define NTILE 1352       // NBt*POS/128 (exact)

// ---- device-global scratch ----
__device__ float          g_Y  [(size_t)NBt*POS*DDc];      // residual stream, fp32
__device__ __nv_bfloat16  g_Ynp[(size_t)NBt*HP*HP*DDc];    // LN out, bf16, zero-padded
__device__ __nv_bfloat16  g_w3T[(size_t)4*9*CHc*DDc];      // [l][tap][co][ci]
__device__ __nv_bfloat16  g_w1T[(size_t)4*DDc*CHc];        // [l][d][co]
__device__ int            g_inv[POS];

// ---------------- PTX helpers (baseline PTX only) ----------------
__device__ __forceinline__ uint32_t s2u(const void* p){
  uint32_t a;
  asm("{ .reg .u64 t; cvta.to.shared.u64 t, %1; cvt.u32.u64 %0, t; }" : "=r"(a) : "l"(p));
  return a;
}
#define CP16(dst, src) asm volatile("cp.async.cg.shared.global [%0], [%1], 16;" :: "r"(dst), "l"(src) : "memory")
#define CP_COMMIT()    asm volatile("cp.async.commit_group;" ::: "memory")
#define CP_WAIT(n)     asm volatile("cp.async.wait_group %0;" :: "n"(n) : "memory")

__device__ __forceinline__ void ldsm4(uint32_t addr, uint32_t &r0, uint32_t &r1, uint32_t &r2, uint32_t &r3){
  asm volatile("ldmatrix.sync.aligned.m8n8.x4.shared.b16 {%0,%1,%2,%3}, [%4];"
    : "=r"(r0),"=r"(r1),"=r"(r2),"=r"(r3) : "r"(addr));
}
__device__ __forceinline__ void mma16816(float* c, uint32_t a0,uint32_t a1,uint32_t a2,uint32_t a3,
                                         uint32_t b0,uint32_t b1){
  asm volatile("mma.sync.aligned.m16n8k16.row.col.f32.bf16.bf16.f32 "
    "{%0,%1,%2,%3}, {%4,%5,%6,%7}, {%8,%9}, {%0,%1,%2,%3};"
    : "+f"(c[0]),"+f"(c[1]),"+f"(c[2]),"+f"(c[3])
    : "r"(a0),"r"(a1),"r"(a2),"r"(a3),"r"(b0),"r"(b1));
}

// ---- packed f32x2 ops ----
typedef unsigned long long u64;
__device__ __forceinline__ u64 pk2(float lo, float hi){
  u64 r; asm("mov.b64 %0, {%1, %2};" : "=l"(r) : "f"(lo), "f"(hi)); return r;
}
__device__ __forceinline__ void upk2(u64 v, float &lo, float &hi){
  asm("mov.b64 {%0, %1}, %2;" : "=f"(lo), "=f"(hi) : "l"(v));
}
__device__ __forceinline__ u64 mul2(u64 a, u64 b){
  u64 r; asm("mul.rn.f32x2 %0, %1, %2;" : "=l"(r) : "l"(a), "l"(b)); return r;
}
__device__ __forceinline__ u64 add2(u64 a, u64 b){
  u64 r; asm("add.rn.f32x2 %0, %1, %2;" : "=l"(r) : "l"(a), "l"(b)); return r;
}
__device__ __forceinline__ u64 fma2(u64 a, u64 b, u64 c){
  u64 r; asm("fma.rn.f32x2 %0, %1, %2, %3;" : "=l"(r) : "l"(a), "l"(b), "l"(c)); return r;
}

// branchless MUFU-free packed gelu: 0.5x(1+tanh(x(c0+c1 x^2))), tanh = Pade 7/6
__device__ __forceinline__ u64 gelu2(float v0, float v1){
  const u64 C0  = pk2(0.79788456f, 0.79788456f);
  const u64 C1  = pk2(0.035677408f, 0.035677408f);
  const u64 K378  = pk2(378.f, 378.f);
  const u64 K17325= pk2(17325.f, 17325.f);
  const u64 K135  = pk2(135135.f, 135135.f);
  const u64 K28   = pk2(28.f, 28.f);
  const u64 K3150 = pk2(3150.f, 3150.f);
  const u64 K62370= pk2(62370.f, 62370.f);
  const u64 NONE  = pk2(-1.f, -1.f);
  const u64 HALF  = pk2(0.5f, 0.5f);

  u64 x  = pk2(v0, v1);
  u64 s  = mul2(x, x);
  u64 z  = mul2(x, fma2(C1, s, C0));
  u64 w  = mul2(z, z);
  u64 num = mul2(z, fma2(w, fma2(w, add2(w, K378), K17325), K135));
  u64 den = fma2(w, fma2(w, fma2(w, K28, K3150), K62370), K135);
  float dl, dh; upk2(den, dl, dh);
  float yl = __int_as_float(0x7EF311C3 - __float_as_int(dl));
  float yh = __int_as_float(0x7EF311C3 - __float_as_int(dh));
  u64 y  = pk2(yl, yh);
  u64 nd = mul2(den, NONE);
  y = mul2(y, fma2(nd, y, pk2(2.f,2.f)));
  y = mul2(y, fma2(nd, y, pk2(2.f,2.f)));
  u64 th = mul2(num, y);
  u64 hx = mul2(x, HALF);
  return fma2(th, hx, hx);       // 0.5x + 0.5x*tanh
}

// ---------------- small kernels ----------------
__global__ void k_inv(const int* __restrict__ coords){
  int t = threadIdx.x;
  if (t < POS) g_inv[t] = -1;
  __syncthreads();
  if (t < LLt){
    int r = coords[2*t], c = coords[2*t+1];
    g_inv[r*26 + c] = t;
  }
}

// merged weight transpose+cast + g_Ynp border zeroing
__global__ void k_prep(const float* __restrict__ w3, const float* __restrict__ w1){
  int blk = blockIdx.x;
  if (blk < 4608){
    int idx = blk*256 + threadIdx.x;
    int ci = idx & 127;
    int co = (idx>>7) & 255;
    int lt = idx>>15;
    g_w3T[idx] = __float2bfloat16(w3[((size_t)lt*128 + ci)*256 + co]);
  } else if (blk < 5120){
    int idx = (blk-4608)*256 + threadIdx.x;
    int co = idx & 255;
    int d  = (idx>>8) & 127;
    int l  = idx>>15;
    g_w1T[idx] = __float2bfloat16(w1[((size_t)l*256 + co)*128 + d]);
  } else {
    int idx = (blk-5120)*256 + threadIdx.x;
    int c2 = idx & 63;
    int j  = (idx >> 6) % 108;
    int b  = (idx >> 6) / 108;
    int r, c;
    if      (j < 28){ r = 0;       c = j; }
    else if (j < 56){ r = 27;      c = j-28; }
    else if (j < 82){ r = j-56+1;  c = 0; }
    else            { r = j-82+1;  c = 27; }
    *(__nv_bfloat162*)(g_Ynp + (((size_t)b*HP + r)*HP + c)*DDc + c2*2) =
        __floats2bfloat162_rn(0.f, 0.f);
  }
}

// fused scatter + layer-0 LN
__global__ void k_fill_ln(const float* __restrict__ X, const float* __restrict__ P,
                          const float* __restrict__ scale, const float* __restrict__ bias){
  int cell = blockIdx.x*8 + (threadIdx.x>>5);
  int lane = threadIdx.x & 31;
  int b = cell/POS, sp = cell - b*POS;
  int li = g_inv[sp];
  const float* src = (li >= 0) ? (X + ((size_t)b*LLt + li)*DDc) : P;
  float v0=src[lane], v1=src[lane+32], v2=src[lane+64], v3=src[lane+96];
  float* y = g_Y + (size_t)cell*DDc;
  y[lane]=v0; y[lane+32]=v1; y[lane+64]=v2; y[lane+96]=v3;
  float s  = v0+v1+v2+v3;
  float s2 = v0*v0+v1*v1+v2*v2+v3*v3;
  #pragma unroll
  for (int o=16;o;o>>=1){ s += __shfl_xor_sync(~0u,s,o); s2 += __shfl_xor_sync(~0u,s2,o); }
  float mn = s*(1.f/128.f);
  float var = s2*(1.f/128.f) - mn*mn;
  float rs = rsqrtf(var + 1e-5f);
  int h = sp/26, w = sp - h*26;
  __nv_bfloat16* o = g_Ynp + (((size_t)b*HP + h+1)*HP + (w+1))*DDc;
  o[lane]    = __float2bfloat16((v0-mn)*rs*scale[lane]    + bias[lane]);
  o[lane+32] = __float2bfloat16((v1-mn)*rs*scale[lane+32] + bias[lane+32]);
  o[lane+64] = __float2bfloat16((v2-mn)*rs*scale[lane+64] + bias[lane+64]);
  o[lane+96] = __float2bfloat16((v3-mn)*rs*scale[lane+96] + bias[lane+96]);
}

// warp-per-cell LayerNorm (layers 1..3)
__global__ void k_ln(const float* __restrict__ scale, const float* __restrict__ bias){
  int cell = blockIdx.x*8 + (threadIdx.x>>5);
  int lane = threadIdx.x & 31;
  const float* x = g_Y + (size_t)cell*DDc;
  float v0=x[lane], v1=x[lane+32], v2=x[lane+64], v3=x[lane+96];
  float s  = v0+v1+v2+v3;
  float s2 = v0*v0+v1*v1+v2*v2+v3*v3;
  #pragma unroll
  for (int o=16;o;o>>=1){ s += __shfl_xor_sync(~0u,s,o); s2 += __shfl_xor_sync(~0u,s2,o); }
  float mn = s*(1.f/128.f);
  float var = s2*(1.f/128.f) - mn*mn;
  float rs = rsqrtf(var + 1e-5f);
  int b = cell/POS, sp = cell - b*POS;
  int h = sp/26, w = sp - h*26;
  __nv_bfloat16* o = g_Ynp + (((size_t)b*HP + h+1)*HP + (w+1))*DDc;
  o[lane]    = __float2bfloat16((v0-mn)*rs*scale[lane]    + bias[lane]);
  o[lane+32] = __float2bfloat16((v1-mn)*rs*scale[lane+32] + bias[lane+32]);
  o[lane+64] = __float2bfloat16((v2-mn)*rs*scale[lane+64] + bias[lane+64]);
  o[lane+96] = __float2bfloat16((v3-mn)*rs*scale[lane+96] + bias[lane+96]);
}

__global__ void k_gather(const int* __restrict__ coords, float* __restrict__ out){
  unsigned idx = blockIdx.x*256u + threadIdx.x;
  int c = idx & (DDc-1);
  int l = (idx >> 7) % LLt;
  int b = (idx >> 7) / LLt;
  int r = coords[2*l], cc = coords[2*l+1];
  out[idx] = g_Y[((size_t)b*POS + r*26 + cc)*DDc + c];
}

// ---------------- fused conv block: halo-A (loaded once) + 16 warps ----------------
__global__ void __launch_bounds__(512,1) k_conv(
    int layer, const float* __restrict__ b3, const float* __restrict__ b1)
{
  extern __shared__ unsigned char smraw[];
  uint32_t sb0 = s2u(smraw);
  uint32_t pad = (0u - sb0) & 1023u;
  unsigned char* smem = smraw + pad;
  const uint32_t sbase = sb0 + pad;

  const int tid = threadIdx.x, lane = tid&31, wid = tid>>5;
  const int wm = wid & 3;          // 4-way M split (32 rows each)
  const int wn = wid >> 2;         // 4-way N split (64 cols each)
  const int lr = lane & 15;
  const int hi = lane >> 4;
  const int sw = lane & 7;

  enum { OFF_CQ=0, OFF_RB=512, OFF_H=1024,
         OFF_B0=1024+71680, OFF_B1=1024+71680+65536 };   // end = 203776

  int* cq0T = (int*)(smem+OFF_CQ);     // per-m halo cell index (window top-left)
  int* rbT  = (int*)(smem+OFF_RB);     // per-slot source row elem offset (<=10)

  // ---- per-tile tables (two-region halo for batch-crossing tiles) ----
  const int tile = blockIdx.x;
  const int p0 = tile*128;
  const int b0 = p0/POS, s0 = p0 - b0*POS, r0 = s0/26;
  const int p127 = p0+127, b127 = p127/POS;
  int K0, Ktot;
  if (b127==b0){ int rl = (p127 - b0*POS)/26; K0 = rl - r0 + 3; Ktot = K0; }
  else { K0 = 28 - r0; int r1e = (p127 - b127*POS)/26; Ktot = K0 + r1e + 3; }

  if (tid < 128){
    int p = p0 + tid;
    int b = p/POS, sp = p - b*POS, r = sp/26, c = sp - r*26;
    int slA = (b==b0) ? (r - r0) : (K0 + r);
    cq0T[tid] = slA*28 + c;
  }
  if (tid < 10){
    int j = tid, boff, pr;
    if (j < K0){ boff = b0; pr = r0 + j; }
    else       { boff = b0+1; pr = j - K0; }
    if (j >= Ktot){ boff = b0; pr = 0; }
    rbT[j] = (boff*HP + pr)*HP*DDc;
  }
  __syncthreads();

  const __nv_bfloat16* w3T = g_w3T + (size_t)layer*9*CHc*DDc;
  const __nv_bfloat16* w1T = g_w1T + (size_t)layer*DDc*CHc;

  // ---- group 0: halo (once) + B tile for tap 0 ----
  {
    const int tot = Ktot*448;                  // 16B chunks in halo
    for (int i = tid; i < tot; i += 512){
      int j = (int)(((unsigned)i) / 448u);
      int rem = i - j*448;
      int cell = rem>>4, c16 = rem&15;
      int q = j*28 + cell;
      uint32_t dst = sbase + OFF_H + (uint32_t)q*256u + (uint32_t)((c16 ^ (q&7))<<4);
      CP16(dst, g_Ynp + (size_t)rbT[j] + cell*DDc + c16*8);
    }
  }
  #pragma unroll
  for (int it=0; it<8; it++){
    int seg = tid + it*512; int row = seg>>4, c = seg&15;
    uint32_t dst = sbase + OFF_B0 + row*256 + ((c ^ (row&7))<<4);
    CP16(dst, w3T + (size_t)row*DDc + c*8);
  }
  CP_COMMIT();

  int cq[2];
  #pragma unroll
  for (int mb=0;mb<2;mb++) cq[mb] = cq0T[wm*32 + mb*16 + lr];

  float acc[2][8][4];
  #pragma unroll
  for (int a=0;a<2;a++)
    #pragma unroll
    for (int b=0;b<8;b++)
      #pragma unroll
      for (int q=0;q<4;q++) acc[a][b][q]=0.f;

  // ---- 9 taps: only B is staged per tap; A ldsm reads shifted halo views ----
  for (int t=0; t<9; t++){
    if (t>0) __syncthreads();
    if (t<8){
      const __nv_bfloat16* wsrc = w3T + (size_t)(t+1)*CHc*DDc;
      const uint32_t boff = ((t+1)&1)? (uint32_t)OFF_B1 : (uint32_t)OFF_B0;
      #pragma unroll
      for (int it=0; it<8; it++){
        int seg = tid + it*512; int row = seg>>4, c = seg&15;
        uint32_t dst = sbase + boff + row*256 + ((c ^ (row&7))<<4);
        CP16(dst, wsrc + (size_t)row*DDc + c*8);
      }
    } else {
      // prefetch w1 tile [128 d][256 co] into B1
      #pragma unroll
      for (int it=0; it<8; it++){
        int seg = tid + it*512; int row = seg>>5, c = seg&31;
        uint32_t dst = sbase + OFF_B1 + row*512 + ((c ^ (row&7))<<4);
        CP16(dst, w1T + (size_t)row*CHc + c*8);
      }
    }
    CP_COMMIT();
    CP_WAIT(1);
    __syncthreads();

    const uint32_t bbuf = sbase + ((t&1)? (uint32_t)OFF_B1 : (uint32_t)OFF_B0);
    const int offt = (t/3)*28 + (t%3);
    uint32_t Abase[2], akey[2];
    #pragma unroll
    for (int mb=0;mb<2;mb++){
      int q = cq[mb] + offt;
      Abase[mb] = sbase + OFF_H + (uint32_t)q*256u;
      akey[mb]  = (uint32_t)(q&7);
    }
    uint32_t Bbase[4];
    #pragma unroll
    for (int nb2=0;nb2<4;nb2++) Bbase[nb2] = bbuf + (wn*64 + nb2*16 + lr)*256;

    #pragma unroll
    for (int kb=0; kb<8; kb++){
      const uint32_t ch = (uint32_t)(2*kb + hi);
      uint32_t a[2][4], bf[4][4];
      #pragma unroll
      for (int mb=0;mb<2;mb++)
        ldsm4(Abase[mb] + ((ch ^ akey[mb])<<4), a[mb][0],a[mb][1],a[mb][2],a[mb][3]);
      #pragma unroll
      for (int nb2=0;nb2<4;nb2++)
        ldsm4(Bbase[nb2] + ((ch ^ (uint32_t)sw)<<4), bf[nb2][0],bf[nb2][1],bf[nb2][2],bf[nb2][3]);
      #pragma unroll
      for (int mb=0;mb<2;mb++){
        #pragma unroll
        for (int nb2=0;nb2<4;nb2++){
          mma16816(acc[mb][2*nb2  ], a[mb][0],a[mb][1],a[mb][2],a[mb][3], bf[nb2][0], bf[nb2][2]);
          mma16816(acc[mb][2*nb2+1], a[mb][0],a[mb][1],a[mb][2],a[mb][3], bf[nb2][1], bf[nb2][3]);
        }
      }
    }
  }
  __syncthreads();   // all warps done reading halo; region reusable for G

  // ---- epilogue 1: bias + packed fast gelu -> bf16 G [128 m][256 k] at OFF_H ----
  {
    const int rq = lane>>2;
    #pragma unroll
    for (int mb=0;mb<2;mb++){
      const int r0r = wm*32 + mb*16 + rq;
      const int r1r = r0r + 8;
      #pragma unroll
      for (int nb=0;nb<8;nb++){
        const int col = wn*64 + nb*8 + 2*(lane&3);
        float2 bv = *(const float2*)(b3 + col);
        u64 g0 = gelu2(acc[mb][nb][0] + bv.x, acc[mb][nb][1] + bv.y);
        u64 g1 = gelu2(acc[mb][nb][2] + bv.x, acc[mb][nb][3] + bv.y);
        float v0, v1, v2, v3;
        upk2(g0, v0, v1);
        upk2(g1, v2, v3);
        const int chunk = col>>3, wb = (col&7)*2;
        uint32_t o0 = (uint32_t)(r0r*512 + ((chunk ^ (r0r&7))<<4) + wb);
        uint32_t o1 = (uint32_t)(r1r*512 + ((chunk ^ (r1r&7))<<4) + wb);
        __nv_bfloat162 h0 = __floats2bfloat162_rn(v0, v1);
        __nv_bfloat162 h1 = __floats2bfloat162_rn(v2, v3);
        *(uint32_t*)(smem + OFF_H + o0) = *(uint32_t*)&h0;
        *(uint32_t*)(smem + OFF_H + o1) = *(uint32_t*)&h1;
      }
    }
  }
  CP_WAIT(0);                            // w1 tile resident
  __syncthreads();                       // G visible to all warps

  // ---- 1x1 GEMM: D2[128,128] = G[128,256] @ w1T^T (warp tile 32x32) ----
  float a2[2][4][4];
  #pragma unroll
  for (int a=0;a<2;a++)
    #pragma unroll
    for (int b=0;b<4;b++)
      #pragma unroll
      for (int q=0;q<4;q++) a2[a][b][q]=0.f;
  {
    uint32_t Gbase[2], Wbase[2];
    #pragma unroll
    for (int mb=0;mb<2;mb++) Gbase[mb] = sbase + OFF_H + (wm*32 + mb*16 + lr)*512;
    #pragma unroll
    for (int nb2=0;nb2<2;nb2++) Wbase[nb2] = sbase + OFF_B1 + (wn*32 + nb2*16 + lr)*512;

    #pragma unroll
    for (int kb=0; kb<16; kb++){
      const uint32_t off = (uint32_t)(((2*kb + hi) ^ sw) << 4);
      uint32_t a[2][4], bf[2][4];
      #pragma unroll
      for (int mb=0;mb<2;mb++) ldsm4(Gbase[mb]+off, a[mb][0],a[mb][1],a[mb][2],a[mb][3]);
      #pragma unroll
      for (int nb2=0;nb2<2;nb2++) ldsm4(Wbase[nb2]+off, bf[nb2][0],bf[nb2][1],bf[nb2][2],bf[nb2][3]);
      #pragma unroll
      for (int mb=0;mb<2;mb++){
        #pragma unroll
        for (int nb2=0;nb2<2;nb2++){
          mma16816(a2[mb][2*nb2  ], a[mb][0],a[mb][1],a[mb][2],a[mb][3], bf[nb2][0], bf[nb2][2]);
          mma16816(a2[mb][2*nb2+1], a[mb][0],a[mb][1],a[mb][2],a[mb][3], bf[nb2][1], bf[nb2][3]);
        }
      }
    }
  }

  // ---- epilogue 2: bias + residual RMW into g_Y ----
  {
    const int rq = lane>>2;
    #pragma unroll
    for (int mb=0;mb<2;mb++){
      const int r0r = wm*32 + mb*16 + rq;
      float* y0 = g_Y + ((size_t)tile*128 + r0r)*DDc;
      #pragma unroll
      for (int nb=0;nb<4;nb++){
        const int d = wn*32 + nb*8 + 2*(lane&3);
        float2 bv = *(const float2*)(b1 + d);
        float2 ya = *(float2*)(y0 + d);
        ya.x += a2[mb][nb][0] + bv.x;
        ya.y += a2[mb][nb][1] + bv.y;
        *(float2*)(y0 + d) = ya;
        float2 yb = *(float2*)(y0 + 8*DDc + d);
        yb.x += a2[mb][nb][2] + bv.x;
        yb.y += a2[mb][nb][3] + bv.y;
        *(float2*)(y0 + 8*DDc + d) = yb;
      }
    }
  }
}

// ---------------- launch ----------------
extern "C" void kernel_launch(void* const* d_in, const int* in_sizes, int n_in,
                              void* d_out, int out_size){
  const float* X        = (const float*)d_in[0];
  const int*   coords   = (const int*)  d_in[1];
  const float* P        = (const float*)d_in[2];
  const float* ln_scale = (const float*)d_in[3];
  const float* ln_bias  = (const float*)d_in[4];
  const float* w3       = (const float*)d_in[5];
  const float* b3       = (const float*)d_in[6];
  const float* w1       = (const float*)d_in[7];
  const float* b1       = (const float*)d_in[8];
  float* out = (float*)d_out;

  const int SMEM_SZ = 203776 + 1024;
  cudaFuncSetAttribute(k_conv, cudaFuncAttributeMaxDynamicSharedMemorySize, SMEM_SZ);

  // launch order keeps index 3 (ncu's sample slot) = k_conv layer 0
  k_inv    <<<1, 1024>>>(coords);                                   // 0
  k_prep   <<<12032, 256>>>(w3, w1);                                // 1
  k_fill_ln<<<21632, 256>>>(X, P, ln_scale, ln_bias);               // 2
  k_conv   <<<NTILE, 512, SMEM_SZ>>>(0, b3, b1);                    // 3  <- profiled
  for (int l=1; l<4; l++){
    k_ln  <<<21632, 256>>>(ln_scale + l*DDc, ln_bias + l*DDc);
    k_conv<<<NTILE, 512, SMEM_SZ>>>(l, b3 + l*CHc, b1 + l*DDc);
  }
  k_gather<<<79872, 256>>>(coords, out);
}

// round 10
// speedup vs baseline: 1.0026x; 1.0026x over previous
#include <cuda_runtime.h>
#include <cuda_bf16.h>
#include <stdint.h>
#include <math.h>

#define NBt 256
#define POS 676          // 26*26
#define LLt 624
#define DDc 128
#define CHc 256
#define HP  28           // padded grid 28x28
#define NTILE 1352       // NBt*POS/128 (exact)

// ---- device-global scratch ----
__device__ float          g_Y  [(size_t)NBt*POS*DDc];      // residual stream, fp32
__device__ __nv_bfloat16  g_Ynp[(size_t)NBt*HP*HP*DDc];    // LN out, bf16, zero-padded
__device__ __nv_bfloat16  g_w3T[(size_t)4*9*CHc*DDc];      // [l][tap][co][ci]
__device__ __nv_bfloat16  g_w1T[(size_t)4*DDc*CHc];        // [l][d][co]
__device__ int            g_inv[POS];

// ---------------- PTX helpers (baseline PTX only) ----------------
__device__ __forceinline__ uint32_t s2u(const void* p){
  uint32_t a;
  asm("{ .reg .u64 t; cvta.to.shared.u64 t, %1; cvt.u32.u64 %0, t; }" : "=r"(a) : "l"(p));
  return a;
}
#define CP16(dst, src) asm volatile("cp.async.cg.shared.global [%0], [%1], 16;" :: "r"(dst), "l"(src) : "memory")
#define CP_COMMIT()    asm volatile("cp.async.commit_group;" ::: "memory")
#define CP_WAIT(n)     asm volatile("cp.async.wait_group %0;" :: "n"(n) : "memory")

__device__ __forceinline__ void ldsm4(uint32_t addr, uint32_t &r0, uint32_t &r1, uint32_t &r2, uint32_t &r3){
  asm volatile("ldmatrix.sync.aligned.m8n8.x4.shared.b16 {%0,%1,%2,%3}, [%4];"
    : "=r"(r0),"=r"(r1),"=r"(r2),"=r"(r3) : "r"(addr));
}
__device__ __forceinline__ void mma16816(float* c, uint32_t a0,uint32_t a1,uint32_t a2,uint32_t a3,
                                         uint32_t b0,uint32_t b1){
  asm volatile("mma.sync.aligned.m16n8k16.row.col.f32.bf16.bf16.f32 "
    "{%0,%1,%2,%3}, {%4,%5,%6,%7}, {%8,%9}, {%0,%1,%2,%3};"
    : "+f"(c[0]),"+f"(c[1]),"+f"(c[2]),"+f"(c[3])
    : "r"(a0),"r"(a1),"r"(a2),"r"(a3),"r"(b0),"r"(b1));
}

// ---- packed f32x2 ops ----
typedef unsigned long long u64;
__device__ __forceinline__ u64 pk2(float lo, float hi){
  u64 r; asm("mov.b64 %0, {%1, %2};" : "=l"(r) : "f"(lo), "f"(hi)); return r;
}
__device__ __forceinline__ void upk2(u64 v, float &lo, float &hi){
  asm("mov.b64 {%0, %1}, %2;" : "=f"(lo), "=f"(hi) : "l"(v));
}
__device__ __forceinline__ u64 mul2(u64 a, u64 b){
  u64 r; asm("mul.rn.f32x2 %0, %1, %2;" : "=l"(r) : "l"(a), "l"(b)); return r;
}
__device__ __forceinline__ u64 add2(u64 a, u64 b){
  u64 r; asm("add.rn.f32x2 %0, %1, %2;" : "=l"(r) : "l"(a), "l"(b)); return r;
}
__device__ __forceinline__ u64 fma2(u64 a, u64 b, u64 c){
  u64 r; asm("fma.rn.f32x2 %0, %1, %2, %3;" : "=l"(r) : "l"(a), "l"(b), "l"(c)); return r;
}

// branchless MUFU-free packed gelu: 0.5x(1+tanh(x(c0+c1 x^2))), tanh = Pade 7/6
__device__ __forceinline__ u64 gelu2(float v0, float v1){
  const u64 C0  = pk2(0.79788456f, 0.79788456f);
  const u64 C1  = pk2(0.035677408f, 0.035677408f);
  const u64 K378  = pk2(378.f, 378.f);
  const u64 K17325= pk2(17325.f, 17325.f);
  const u64 K135  = pk2(135135.f, 135135.f);
  const u64 K28   = pk2(28.f, 28.f);
  const u64 K3150 = pk2(3150.f, 3150.f);
  const u64 K62370= pk2(62370.f, 62370.f);
  const u64 NONE  = pk2(-1.f, -1.f);
  const u64 HALF  = pk2(0.5f, 0.5f);

  u64 x  = pk2(v0, v1);
  u64 s  = mul2(x, x);
  u64 z  = mul2(x, fma2(C1, s, C0));
  u64 w  = mul2(z, z);
  u64 num = mul2(z, fma2(w, fma2(w, add2(w, K378), K17325), K135));
  u64 den = fma2(w, fma2(w, fma2(w, K28, K3150), K62370), K135);
  float dl, dh; upk2(den, dl, dh);
  float yl = __int_as_float(0x7EF311C3 - __float_as_int(dl));
  float yh = __int_as_float(0x7EF311C3 - __float_as_int(dh));
  u64 y  = pk2(yl, yh);
  u64 nd = mul2(den, NONE);
  y = mul2(y, fma2(nd, y, pk2(2.f,2.f)));
  y = mul2(y, fma2(nd, y, pk2(2.f,2.f)));
  u64 th = mul2(num, y);
  u64 hx = mul2(x, HALF);
  return fma2(th, hx, hx);       // 0.5x + 0.5x*tanh
}

// ---------------- small kernels ----------------
__global__ void k_inv(const int* __restrict__ coords){
  int t = threadIdx.x;
  if (t < POS) g_inv[t] = -1;
  __syncthreads();
  if (t < LLt){
    int r = coords[2*t], c = coords[2*t+1];
    g_inv[r*26 + c] = t;
  }
}

// merged weight transpose+cast + g_Ynp border zeroing
__global__ void k_prep(const float* __restrict__ w3, const float* __restrict__ w1){
  int blk = blockIdx.x;
  if (blk < 4608){
    int idx = blk*256 + threadIdx.x;
    int ci = idx & 127;
    int co = (idx>>7) & 255;
    int lt = idx>>15;
    g_w3T[idx] = __float2bfloat16(w3[((size_t)lt*128 + ci)*256 + co]);
  } else if (blk < 5120){
    int idx = (blk-4608)*256 + threadIdx.x;
    int co = idx & 255;
    int d  = (idx>>8) & 127;
    int l  = idx>>15;
    g_w1T[idx] = __float2bfloat16(w1[((size_t)l*256 + co)*128 + d]);
  } else {
    int idx = (blk-5120)*256 + threadIdx.x;
    int c2 = idx & 63;
    int j  = (idx >> 6) % 108;
    int b  = (idx >> 6) / 108;
    int r, c;
    if      (j < 28){ r = 0;       c = j; }
    else if (j < 56){ r = 27;      c = j-28; }
    else if (j < 82){ r = j-56+1;  c = 0; }
    else            { r = j-82+1;  c = 27; }
    *(__nv_bfloat162*)(g_Ynp + (((size_t)b*HP + r)*HP + c)*DDc + c2*2) =
        __floats2bfloat162_rn(0.f, 0.f);
  }
}

// fused scatter + layer-0 LN
__global__ void k_fill_ln(const float* __restrict__ X, const float* __restrict__ P,
                          const float* __restrict__ scale, const float* __restrict__ bias){
  int cell = blockIdx.x*8 + (threadIdx.x>>5);
  int lane = threadIdx.x & 31;
  int b = cell/POS, sp = cell - b*POS;
  int li = g_inv[sp];
  const float* src = (li >= 0) ? (X + ((size_t)b*LLt + li)*DDc) : P;
  float v0=src[lane], v1=src[lane+32], v2=src[lane+64], v3=src[lane+96];
  float* y = g_Y + (size_t)cell*DDc;
  y[lane]=v0; y[lane+32]=v1; y[lane+64]=v2; y[lane+96]=v3;
  float s  = v0+v1+v2+v3;
  float s2 = v0*v0+v1*v1+v2*v2+v3*v3;
  #pragma unroll
  for (int o=16;o;o>>=1){ s += __shfl_xor_sync(~0u,s,o); s2 += __shfl_xor_sync(~0u,s2,o); }
  float mn = s*(1.f/128.f);
  float var = s2*(1.f/128.f) - mn*mn;
  float rs = rsqrtf(var + 1e-5f);
  int h = sp/26, w = sp - h*26;
  __nv_bfloat16* o = g_Ynp + (((size_t)b*HP + h+1)*HP + (w+1))*DDc;
  o[lane]    = __float2bfloat16((v0-mn)*rs*scale[lane]    + bias[lane]);
  o[lane+32] = __float2bfloat16((v1-mn)*rs*scale[lane+32] + bias[lane+32]);
  o[lane+64] = __float2bfloat16((v2-mn)*rs*scale[lane+64] + bias[lane+64]);
  o[lane+96] = __float2bfloat16((v3-mn)*rs*scale[lane+96] + bias[lane+96]);
}

// warp-per-cell LayerNorm (layers 1..3)
__global__ void k_ln(const float* __restrict__ scale, const float* __restrict__ bias){
  int cell = blockIdx.x*8 + (threadIdx.x>>5);
  int lane = threadIdx.x & 31;
  const float* x = g_Y + (size_t)cell*DDc;
  float v0=x[lane], v1=x[lane+32], v2=x[lane+64], v3=x[lane+96];
  float s  = v0+v1+v2+v3;
  float s2 = v0*v0+v1*v1+v2*v2+v3*v3;
  #pragma unroll
  for (int o=16;o;o>>=1){ s += __shfl_xor_sync(~0u,s,o); s2 += __shfl_xor_sync(~0u,s2,o); }
  float mn = s*(1.f/128.f);
  float var = s2*(1.f/128.f) - mn*mn;
  float rs = rsqrtf(var + 1e-5f);
  int b = cell/POS, sp = cell - b*POS;
  int h = sp/26, w = sp - h*26;
  __nv_bfloat16* o = g_Ynp + (((size_t)b*HP + h+1)*HP + (w+1))*DDc;
  o[lane]    = __float2bfloat16((v0-mn)*rs*scale[lane]    + bias[lane]);
  o[lane+32] = __float2bfloat16((v1-mn)*rs*scale[lane+32] + bias[lane+32]);
  o[lane+64] = __float2bfloat16((v2-mn)*rs*scale[lane+64] + bias[lane+64]);
  o[lane+96] = __float2bfloat16((v3-mn)*rs*scale[lane+96] + bias[lane+96]);
}

__global__ void k_gather(const int* __restrict__ coords, float* __restrict__ out){
  unsigned idx = blockIdx.x*256u + threadIdx.x;
  int c = idx & (DDc-1);
  int l = (idx >> 7) % LLt;
  int b = (idx >> 7) / LLt;
  int r = coords[2*l], cc = coords[2*l+1];
  out[idx] = g_Y[((size_t)b*POS + r*26 + cc)*DDc + c];
}

// ---------------- fused conv block: 8 warps, 64x64 tiles, pipelined fragments ----------------
__global__ void __launch_bounds__(256,1) k_conv(
    int layer, const float* __restrict__ b3, const float* __restrict__ b1)
{
  extern __shared__ unsigned char smraw[];
  uint32_t sb0 = s2u(smraw);
  uint32_t pad = (0u - sb0) & 1023u;
  unsigned char* smem = smraw + pad;
  const uint32_t sbase = sb0 + pad;

  const int tid = threadIdx.x, lane = tid&31, wid = tid>>5;
  const int wm = wid & 1;          // 2-way M split (64 rows each)
  const int wn = wid >> 1;         // 4-way N split (64 cols each)
  const int lr = lane & 15;
  const int hi = lane >> 4;
  const int sw = lane & 7;

  enum { OFF_TAB=0, OFF_A0=1024, OFF_A1=1024+32768,
         OFF_B0=1024+65536, OFF_B1=1024+65536+65536 };   // end = 197632

  int* baseT = (int*)(smem + OFF_TAB);
  if (tid < 128){
    int p = blockIdx.x*128 + tid;
    int b = p/POS, sp = p - b*POS;
    int r = sp/26, c = sp - r*26;
    baseT[tid] = ((b*HP + r)*HP + c)*DDc;     // 3x3 window top-left elem offset
  }
  __syncthreads();

  const __nv_bfloat16* w3T = g_w3T + (size_t)layer*9*CHc*DDc;
  const __nv_bfloat16* w1T = g_w1T + (size_t)layer*DDc*CHc;

  #define LOAD_TAP(T_, AOFF, BOFF) do{                                          \
    const int tapoff = (((T_)/3)*HP + ((T_)%3))*DDc;                             \
    _Pragma("unroll")                                                            \
    for (int it=0; it<8; it++){                                                  \
      int seg = tid + it*256; int m = seg>>4, c = seg&15;                        \
      const __nv_bfloat16* src = g_Ynp + (size_t)(baseT[m] + tapoff) + c*8;      \
      uint32_t dst = sbase + (AOFF) + m*256 + ((c ^ (m&7))<<4);                  \
      CP16(dst, src);                                                            \
    }                                                                            \
    const __nv_bfloat16* wsrc = w3T + (size_t)(T_)*CHc*DDc;                      \
    _Pragma("unroll")                                                            \
    for (int it=0; it<16; it++){                                                 \
      int seg = tid + it*256; int row = seg>>4, c = seg&15;                      \
      uint32_t dst = sbase + (BOFF) + row*256 + ((c ^ (row&7))<<4);              \
      CP16(dst, wsrc + (size_t)row*DDc + c*8);                                   \
    }                                                                            \
  }while(0)

  float acc[4][8][4];
  #pragma unroll
  for (int a=0;a<4;a++)
    #pragma unroll
    for (int b=0;b<8;b++)
      #pragma unroll
      for (int q=0;q<4;q++) acc[a][b][q]=0.f;

  LOAD_TAP(0, OFF_A0, OFF_B0); CP_COMMIT();

  for (int t=0; t<9; t++){
    if (t>0) __syncthreads();
    if (t<8){
      if ((t+1)&1) LOAD_TAP(t+1, OFF_A1, OFF_B1);
      else         LOAD_TAP(t+1, OFF_A0, OFF_B0);
      CP_COMMIT();
    } else {
      // prefetch w1 tile [128 d][256 co] into B1
      #pragma unroll
      for (int it=0; it<16; it++){
        int seg = tid + it*256; int row = seg>>5, c = seg&31;
        uint32_t dst = sbase + OFF_B1 + row*512 + ((c ^ (row&7))<<4);
        CP16(dst, w1T + (size_t)row*CHc + c*8);
      }
      CP_COMMIT();
    }
    CP_WAIT(1);
    __syncthreads();

    const uint32_t abuf = sbase + ((t&1)? OFF_A1 : OFF_A0);
    const uint32_t bbuf = sbase + ((t&1)? OFF_B1 : OFF_B0);
    uint32_t Abase[4], Bbase[4];
    #pragma unroll
    for (int mb=0;mb<4;mb++) Abase[mb] = abuf + (wm*64 + mb*16 + lr)*256;
    #pragma unroll
    for (int nb2=0;nb2<4;nb2++) Bbase[nb2] = bbuf + (wn*64 + nb2*16 + lr)*256;

    // software-pipelined fragments: load kb+1 while issuing kb's 32 HMMAs
    uint32_t a[2][4][4], bf[2][4][4];
    {
      const uint32_t off0 = (uint32_t)((hi ^ sw) << 4);
      #pragma unroll
      for (int mb=0;mb<4;mb++) ldsm4(Abase[mb]+off0, a[0][mb][0],a[0][mb][1],a[0][mb][2],a[0][mb][3]);
      #pragma unroll
      for (int nb2=0;nb2<4;nb2++) ldsm4(Bbase[nb2]+off0, bf[0][nb2][0],bf[0][nb2][1],bf[0][nb2][2],bf[0][nb2][3]);
    }
    #pragma unroll
    for (int kb=0; kb<8; kb++){
      const int cur = kb&1, nxt = cur^1;
      if (kb<7){
        const uint32_t offn = (uint32_t)(((2*(kb+1) + hi) ^ sw) << 4);
        #pragma unroll
        for (int mb=0;mb<4;mb++) ldsm4(Abase[mb]+offn, a[nxt][mb][0],a[nxt][mb][1],a[nxt][mb][2],a[nxt][mb][3]);
        #pragma unroll
        for (int nb2=0;nb2<4;nb2++) ldsm4(Bbase[nb2]+offn, bf[nxt][nb2][0],bf[nxt][nb2][1],bf[nxt][nb2][2],bf[nxt][nb2][3]);
      }
      #pragma unroll
      for (int mb=0;mb<4;mb++){
        #pragma unroll
        for (int nb2=0;nb2<4;nb2++){
          mma16816(acc[mb][2*nb2  ], a[cur][mb][0],a[cur][mb][1],a[cur][mb][2],a[cur][mb][3], bf[cur][nb2][0], bf[cur][nb2][2]);
          mma16816(acc[mb][2*nb2+1], a[cur][mb][0],a[cur][mb][1],a[cur][mb][2],a[cur][mb][3], bf[cur][nb2][1], bf[cur][nb2][3]);
        }
      }
    }
  }
  __syncthreads();

  // ---- epilogue 1: bias + packed fast gelu -> bf16 G [128 m][256 k] at OFF_A0 ----
  {
    const int rq = lane>>2;
    #pragma unroll
    for (int mb=0;mb<4;mb++){
      const int r0 = wm*64 + mb*16 + rq;
      const int r1 = r0 + 8;
      #pragma unroll
      for (int nb=0;nb<8;nb++){
        const int col = wn*64 + nb*8 + 2*(lane&3);
        float2 bv = *(const float2*)(b3 + col);
        u64 g0 = gelu2(acc[mb][nb][0] + bv.x, acc[mb][nb][1] + bv.y);
        u64 g1 = gelu2(acc[mb][nb][2] + bv.x, acc[mb][nb][3] + bv.y);
        float v0, v1, v2, v3;
        upk2(g0, v0, v1);
        upk2(g1, v2, v3);
        const int chunk = col>>3, wb = (col&7)*2;
        uint32_t o0 = (uint32_t)(r0*512 + ((chunk ^ (r0&7))<<4) + wb);
        uint32_t o1 = (uint32_t)(r1*512 + ((chunk ^ (r1&7))<<4) + wb);
        __nv_bfloat162 h0 = __floats2bfloat162_rn(v0, v1);
        __nv_bfloat162 h1 = __floats2bfloat162_rn(v2, v3);
        *(uint32_t*)(smem + OFF_A0 + o0) = *(uint32_t*)&h0;
        *(uint32_t*)(smem + OFF_A0 + o1) = *(uint32_t*)&h1;
      }
    }
  }
  CP_WAIT(0);                            // w1 tile resident
  __syncthreads();                       // G visible to all warps

  // ---- 1x1 GEMM: D2[128,128] = G[128,256] @ w1T^T (warp tile 64x32) ----
  float a2[4][4][4];
  #pragma unroll
  for (int a=0;a<4;a++)
    #pragma unroll
    for (int b=0;b<4;b++)
      #pragma unroll
      for (int q=0;q<4;q++) a2[a][b][q]=0.f;
  {
    uint32_t Gbase[4], Wbase[2];
    #pragma unroll
    for (int mb=0;mb<4;mb++) Gbase[mb] = sbase + OFF_A0 + (wm*64 + mb*16 + lr)*512;
    #pragma unroll
    for (int nb2=0;nb2<2;nb2++) Wbase[nb2] = sbase + OFF_B1 + (wn*32 + nb2*16 + lr)*512;

    #pragma unroll
    for (int kb=0; kb<16; kb++){
      const uint32_t off = (uint32_t)(((2*kb + hi) ^ sw) << 4);
      uint32_t a[4][4], bf[2][4];
      #pragma unroll
      for (int mb=0;mb<4;mb++) ldsm4(Gbase[mb]+off, a[mb][0],a[mb][1],a[mb][2],a[mb][3]);
      #pragma unroll
      for (int nb2=0;nb2<2;nb2++) ldsm4(Wbase[nb2]+off, bf[nb2][0],bf[nb2][1],bf[nb2][2],bf[nb2][3]);
      #pragma unroll
      for (int mb=0;mb<4;mb++){
        #pragma unroll
        for (int nb2=0;nb2<2;nb2++){
          mma16816(a2[mb][2*nb2  ], a[mb][0],a[mb][1],a[mb][2],a[mb][3], bf[nb2][0], bf[nb2][2]);
          mma16816(a2[mb][2*nb2+1], a[mb][0],a[mb][1],a[mb][2],a[mb][3], bf[nb2][1], bf[nb2][3]);
        }
      }
    }
  }

  // ---- epilogue 2: bias + residual RMW into g_Y ----
  {
    const int rq = lane>>2;
    #pragma unroll
    for (int mb=0;mb<4;mb++){
      const int r0 = wm*64 + mb*16 + rq;
      float* y0 = g_Y + ((size_t)blockIdx.x*128 + r0)*DDc;
      #pragma unroll
      for (int nb=0;nb<4;nb++){
        const int d = wn*32 + nb*8 + 2*(lane&3);
        float2 bv = *(const float2*)(b1 + d);
        float2 ya = *(float2*)(y0 + d);
        ya.x += a2[mb][nb][0] + bv.x;
        ya.y += a2[mb][nb][1] + bv.y;
        *(float2*)(y0 + d) = ya;
        float2 yb = *(float2*)(y0 + 8*DDc + d);
        yb.x += a2[mb][nb][2] + bv.x;
        yb.y += a2[mb][nb][3] + bv.y;
        *(float2*)(y0 + 8*DDc + d) = yb;
      }
    }
  }
  #undef LOAD_TAP
}

// ---------------- launch ----------------
extern "C" void kernel_launch(void* const* d_in, const int* in_sizes, int n_in,
                              void* d_out, int out_size){
  const float* X        = (const float*)d_in[0];
  const int*   coords   = (const int*)  d_in[1];
  const float* P        = (const float*)d_in[2];
  const float* ln_scale = (const float*)d_in[3];
  const float* ln_bias  = (const float*)d_in[4];
  const float* w3       = (const float*)d_in[5];
  const float* b3       = (const float*)d_in[6];
  const float* w1       = (const float*)d_in[7];
  const float* b1       = (const float*)d_in[8];
  float* out = (float*)d_out;

  const int SMEM_SZ = 197632 + 1024;
  cudaFuncSetAttribute(k_conv, cudaFuncAttributeMaxDynamicSharedMemorySize, SMEM_SZ);

  // launch order keeps index 3 (ncu's sample slot) = k_conv layer 0
  k_inv    <<<1, 1024>>>(coords);                                   // 0
  k_prep   <<<12032, 256>>>(w3, w1);                                // 1
  k_fill_ln<<<21632, 256>>>(X, P, ln_scale, ln_bias);               // 2
  k_conv   <<<NTILE, 256, SMEM_SZ>>>(0, b3, b1);                    // 3  <- profiled
  for (int l=1; l<4; l++){
    k_ln  <<<21632, 256>>>(ln_scale + l*DDc, ln_bias + l*DDc);
    k_conv<<<NTILE, 256, SMEM_SZ>>>(l, b3 + l*CHc, b1 + l*DDc);
  }
  k_gather<<<79872, 256>>>(coords, out);
}

// round 11
// speedup vs baseline: 1.0472x; 1.0445x over previous
#include <cuda_runtime.h>
#include <cuda_bf16.h>
#include <stdint.h>
#include <math.h>

#define NBt 256
#define POS 676          // 26*26
#define LLt 624
#define DDc 128
#define CHc 256
#define HP  28           // padded grid 28x28
#define NTILE 1352       // NBt*POS/128 (exact)

typedef unsigned long long u64;

// ---- device-global scratch ----
__device__ float          g_Y  [(size_t)NBt*POS*DDc];      // residual stream, fp32
__device__ __nv_bfloat16  g_Ynp[(size_t)NBt*HP*HP*DDc];    // LN out, bf16, zero-padded
__device__ u64            g_w3F[(size_t)4*9*8*32*32];      // fragment-major conv weights
__device__ __nv_bfloat16  g_w1T[(size_t)4*DDc*CHc];        // [l][d][co]
__device__ int            g_inv[POS];

// ---------------- PTX helpers (baseline PTX only) ----------------
__device__ __forceinline__ uint32_t s2u(const void* p){
  uint32_t a;
  asm("{ .reg .u64 t; cvta.to.shared.u64 t, %1; cvt.u32.u64 %0, t; }" : "=r"(a) : "l"(p));
  return a;
}
#define CP16(dst, src) asm volatile("cp.async.cg.shared.global [%0], [%1], 16;" :: "r"(dst), "l"(src) : "memory")
#define CP_COMMIT()    asm volatile("cp.async.commit_group;" ::: "memory")
#define CP_WAIT(n)     asm volatile("cp.async.wait_group %0;" :: "n"(n) : "memory")

__device__ __forceinline__ void ldsm4(uint32_t addr, uint32_t &r0, uint32_t &r1, uint32_t &r2, uint32_t &r3){
  asm volatile("ldmatrix.sync.aligned.m8n8.x4.shared.b16 {%0,%1,%2,%3}, [%4];"
    : "=r"(r0),"=r"(r1),"=r"(r2),"=r"(r3) : "r"(addr));
}
__device__ __forceinline__ void ldg2(const u64* p, uint32_t &r0, uint32_t &r1){
  asm volatile("ld.global.nc.v2.b32 {%0,%1}, [%2];" : "=r"(r0), "=r"(r1) : "l"(p));
}
__device__ __forceinline__ void mma16816(float* c, uint32_t a0,uint32_t a1,uint32_t a2,uint32_t a3,
                                         uint32_t b0,uint32_t b1){
  asm volatile("mma.sync.aligned.m16n8k16.row.col.f32.bf16.bf16.f32 "
    "{%0,%1,%2,%3}, {%4,%5,%6,%7}, {%8,%9}, {%0,%1,%2,%3};"
    : "+f"(c[0]),"+f"(c[1]),"+f"(c[2]),"+f"(c[3])
    : "r"(a0),"r"(a1),"r"(a2),"r"(a3),"r"(b0),"r"(b1));
}

// ---- packed f32x2 ops ----
__device__ __forceinline__ u64 pk2(float lo, float hi){
  u64 r; asm("mov.b64 %0, {%1, %2};" : "=l"(r) : "f"(lo), "f"(hi)); return r;
}
__device__ __forceinline__ void upk2(u64 v, float &lo, float &hi){
  asm("mov.b64 {%0, %1}, %2;" : "=f"(lo), "=f"(hi) : "l"(v));
}
__device__ __forceinline__ u64 mul2(u64 a, u64 b){
  u64 r; asm("mul.rn.f32x2 %0, %1, %2;" : "=l"(r) : "l"(a), "l"(b)); return r;
}
__device__ __forceinline__ u64 add2(u64 a, u64 b){
  u64 r; asm("add.rn.f32x2 %0, %1, %2;" : "=l"(r) : "l"(a), "l"(b)); return r;
}
__device__ __forceinline__ u64 fma2(u64 a, u64 b, u64 c){
  u64 r; asm("fma.rn.f32x2 %0, %1, %2, %3;" : "=l"(r) : "l"(a), "l"(b), "l"(c)); return r;
}

// branchless MUFU-free packed gelu: 0.5x(1+tanh(x(c0+c1 x^2))), tanh = Pade 7/6
__device__ __forceinline__ u64 gelu2(float v0, float v1){
  const u64 C0  = pk2(0.79788456f, 0.79788456f);
  const u64 C1  = pk2(0.035677408f, 0.035677408f);
  const u64 K378  = pk2(378.f, 378.f);
  const u64 K17325= pk2(17325.f, 17325.f);
  const u64 K135  = pk2(135135.f, 135135.f);
  const u64 K28   = pk2(28.f, 28.f);
  const u64 K3150 = pk2(3150.f, 3150.f);
  const u64 K62370= pk2(62370.f, 62370.f);
  const u64 NONE  = pk2(-1.f, -1.f);
  const u64 HALF  = pk2(0.5f, 0.5f);

  u64 x  = pk2(v0, v1);
  u64 s  = mul2(x, x);
  u64 z  = mul2(x, fma2(C1, s, C0));
  u64 w  = mul2(z, z);
  u64 num = mul2(z, fma2(w, fma2(w, add2(w, K378), K17325), K135));
  u64 den = fma2(w, fma2(w, fma2(w, K28, K3150), K62370), K135);
  float dl, dh; upk2(den, dl, dh);
  float yl = __int_as_float(0x7EF311C3 - __float_as_int(dl));
  float yh = __int_as_float(0x7EF311C3 - __float_as_int(dh));
  u64 y  = pk2(yl, yh);
  u64 nd = mul2(den, NONE);
  y = mul2(y, fma2(nd, y, pk2(2.f,2.f)));
  y = mul2(y, fma2(nd, y, pk2(2.f,2.f)));
  u64 th = mul2(num, y);
  u64 hx = mul2(x, HALF);
  return fma2(th, hx, hx);       // 0.5x + 0.5x*tanh
}

// ---------------- small kernels ----------------
__global__ void k_inv(const int* __restrict__ coords){
  int t = threadIdx.x;
  if (t < POS) g_inv[t] = -1;
  __syncthreads();
  if (t < LLt){
    int r = coords[2*t], c = coords[2*t+1];
    g_inv[r*26 + c] = t;
  }
}

// merged weight prep: blocks [0,1152): w3 fragment pack   [1152,1664): w1T
//                      [1664,8576): g_Ynp border zeroing
__global__ void k_prep(const float* __restrict__ w3, const float* __restrict__ w1){
  int blk = blockIdx.x;
  if (blk < 1152){
    int idx = blk*256 + threadIdx.x;        // [0, 294912)
    int lane = idx & 31;
    int cc   = (idx>>5) & 31;
    int kb   = (idx>>10) & 7;
    int lt   = idx>>13;                     // l*9 + tap, [0,36)
    int n  = cc*8 + (lane>>2);
    int k0 = kb*16 + 2*(lane&3);
    const float* wbase = w3 + (size_t)lt*32768;   // [ci=128][co=256]
    __nv_bfloat162 lo2 = __floats2bfloat162_rn(wbase[(size_t)k0*256 + n],
                                               wbase[(size_t)(k0+1)*256 + n]);
    __nv_bfloat162 hi2 = __floats2bfloat162_rn(wbase[(size_t)(k0+8)*256 + n],
                                               wbase[(size_t)(k0+9)*256 + n]);
    uint32_t u0 = *(uint32_t*)&lo2, u1 = *(uint32_t*)&hi2;
    g_w3F[idx] = ((u64)u1<<32) | (u64)u0;   // v2.b32 load: r0=u0 (b0), r1=u1 (b1)
  } else if (blk < 1664){
    int idx = (blk-1152)*256 + threadIdx.x; // [0, 131072)
    int co = idx & 255;
    int d  = (idx>>8) & 127;
    int l  = idx>>15;
    g_w1T[idx] = __float2bfloat16(w1[((size_t)l*256 + co)*128 + d]);
  } else {
    int idx = (blk-1664)*256 + threadIdx.x; // 256*108*64 entries
    int c2 = idx & 63;
    int j  = (idx >> 6) % 108;
    int b  = (idx >> 6) / 108;
    int r, c;
    if      (j < 28){ r = 0;       c = j; }
    else if (j < 56){ r = 27;      c = j-28; }
    else if (j < 82){ r = j-56+1;  c = 0; }
    else            { r = j-82+1;  c = 27; }
    *(__nv_bfloat162*)(g_Ynp + (((size_t)b*HP + r)*HP + c)*DDc + c2*2) =
        __floats2bfloat162_rn(0.f, 0.f);
  }
}

// fused scatter + layer-0 LN
__global__ void k_fill_ln(const float* __restrict__ X, const float* __restrict__ P,
                          const float* __restrict__ scale, const float* __restrict__ bias){
  int cell = blockIdx.x*8 + (threadIdx.x>>5);
  int lane = threadIdx.x & 31;
  int b = cell/POS, sp = cell - b*POS;
  int li = g_inv[sp];
  const float* src = (li >= 0) ? (X + ((size_t)b*LLt + li)*DDc) : P;
  float v0=src[lane], v1=src[lane+32], v2=src[lane+64], v3=src[lane+96];
  float* y = g_Y + (size_t)cell*DDc;
  y[lane]=v0; y[lane+32]=v1; y[lane+64]=v2; y[lane+96]=v3;
  float s  = v0+v1+v2+v3;
  float s2 = v0*v0+v1*v1+v2*v2+v3*v3;
  #pragma unroll
  for (int o=16;o;o>>=1){ s += __shfl_xor_sync(~0u,s,o); s2 += __shfl_xor_sync(~0u,s2,o); }
  float mn = s*(1.f/128.f);
  float var = s2*(1.f/128.f) - mn*mn;
  float rs = rsqrtf(var + 1e-5f);
  int h = sp/26, w = sp - h*26;
  __nv_bfloat16* o = g_Ynp + (((size_t)b*HP + h+1)*HP + (w+1))*DDc;
  o[lane]    = __float2bfloat16((v0-mn)*rs*scale[lane]    + bias[lane]);
  o[lane+32] = __float2bfloat16((v1-mn)*rs*scale[lane+32] + bias[lane+32]);
  o[lane+64] = __float2bfloat16((v2-mn)*rs*scale[lane+64] + bias[lane+64]);
  o[lane+96] = __float2bfloat16((v3-mn)*rs*scale[lane+96] + bias[lane+96]);
}

// warp-per-cell LayerNorm (layers 1..3)
__global__ void k_ln(const float* __restrict__ scale, const float* __restrict__ bias){
  int cell = blockIdx.x*8 + (threadIdx.x>>5);
  int lane = threadIdx.x & 31;
  const float* x = g_Y + (size_t)cell*DDc;
  float v0=x[lane], v1=x[lane+32], v2=x[lane+64], v3=x[lane+96];
  float s  = v0+v1+v2+v3;
  float s2 = v0*v0+v1*v1+v2*v2+v3*v3;
  #pragma unroll
  for (int o=16;o;o>>=1){ s += __shfl_xor_sync(~0u,s,o); s2 += __shfl_xor_sync(~0u,s2,o); }
  float mn = s*(1.f/128.f);
  float var = s2*(1.f/128.f) - mn*mn;
  float rs = rsqrtf(var + 1e-5f);
  int b = cell/POS, sp = cell - b*POS;
  int h = sp/26, w = sp - h*26;
  __nv_bfloat16* o = g_Ynp + (((size_t)b*HP + h+1)*HP + (w+1))*DDc;
  o[lane]    = __float2bfloat16((v0-mn)*rs*scale[lane]    + bias[lane]);
  o[lane+32] = __float2bfloat16((v1-mn)*rs*scale[lane+32] + bias[lane+32]);
  o[lane+64] = __float2bfloat16((v2-mn)*rs*scale[lane+64] + bias[lane+64]);
  o[lane+96] = __float2bfloat16((v3-mn)*rs*scale[lane+96] + bias[lane+96]);
}

__global__ void k_gather(const int* __restrict__ coords, float* __restrict__ out){
  unsigned idx = blockIdx.x*256u + threadIdx.x;
  int c = idx & (DDc-1);
  int l = (idx >> 7) % LLt;
  int b = (idx >> 7) / LLt;
  int r = coords[2*l], cc = coords[2*l+1];
  out[idx] = g_Y[((size_t)b*POS + r*26 + cc)*DDc + c];
}

// ---------------- fused conv block: 16 warps; B via direct fragment LDG ----------------
__global__ void __launch_bounds__(512,1) k_conv(
    int layer, const float* __restrict__ b3, const float* __restrict__ b1)
{
  extern __shared__ unsigned char smraw[];
  uint32_t sb0 = s2u(smraw);
  uint32_t pad = (0u - sb0) & 1023u;
  unsigned char* smem = smraw + pad;
  const uint32_t sbase = sb0 + pad;

  const int tid = threadIdx.x, lane = tid&31, wid = tid>>5;
  const int wm = wid & 3;          // 4-way M split (32 rows each)
  const int wn = wid >> 2;         // 4-way N split (64 cols each)
  const int lr = lane & 15;
  const int hi = lane >> 4;
  const int sw = lane & 7;

  enum { OFF_TAB=0, OFF_A0=1024, OFF_A1=1024+32768,
         OFF_W=1024+65536 };                         // end = 132096

  int* baseT = (int*)(smem + OFF_TAB);
  if (tid < 128){
    int p = blockIdx.x*128 + tid;
    int b = p/POS, sp = p - b*POS;
    int r = sp/26, c = sp - r*26;
    baseT[tid] = ((b*HP + r)*HP + c)*DDc;     // 3x3 window top-left elem offset
  }
  __syncthreads();

  const u64* w3F = g_w3F + (size_t)layer*9*8192;
  const __nv_bfloat16* w1T = g_w1T + (size_t)layer*DDc*CHc;

  #define LOAD_A(T_, AOFF) do{                                                  \
    const int tapoff = (((T_)/3)*HP + ((T_)%3))*DDc;                             \
    _Pragma("unroll")                                                            \
    for (int it=0; it<4; it++){                                                  \
      int seg = tid + it*512; int m = seg>>4, c = seg&15;                        \
      const __nv_bfloat16* src = g_Ynp + (size_t)(baseT[m] + tapoff) + c*8;      \
      uint32_t dst = sbase + (AOFF) + m*256 + ((c ^ (m&7))<<4);                  \
      CP16(dst, src);                                                            \
    }                                                                            \
  }while(0)

  float acc[2][8][4];
  #pragma unroll
  for (int a=0;a<2;a++)
    #pragma unroll
    for (int b=0;b<8;b++)
      #pragma unroll
      for (int q=0;q<4;q++) acc[a][b][q]=0.f;

  LOAD_A(0, OFF_A0); CP_COMMIT();

  for (int t=0; t<9; t++){
    if (t>0) __syncthreads();
    if (t<8){
      if ((t+1)&1) LOAD_A(t+1, OFF_A1);
      else         LOAD_A(t+1, OFF_A0);
      CP_COMMIT();
    } else {
      // prefetch w1 tile [128 d][256 co] into OFF_W
      #pragma unroll
      for (int it=0; it<8; it++){
        int seg = tid + it*512; int row = seg>>5, c = seg&31;
        uint32_t dst = sbase + OFF_W + row*512 + ((c ^ (row&7))<<4);
        CP16(dst, w1T + (size_t)row*CHc + c*8);
      }
      CP_COMMIT();
    }
    CP_WAIT(1);
    __syncthreads();

    const uint32_t abuf = sbase + ((t&1)? OFF_A1 : OFF_A0);
    uint32_t Abase[2];
    #pragma unroll
    for (int mb=0;mb<2;mb++) Abase[mb] = abuf + (wm*32 + mb*16 + lr)*256;

    // B fragment pointer for this warp/tap: [kb][cc][lane] u64
    const u64* wt = w3F + (size_t)t*8192 + wn*256 + lane;

    #pragma unroll
    for (int kb=0; kb<8; kb++){
      uint32_t bfr[8][2];
      #pragma unroll
      for (int j=0;j<8;j++) ldg2(wt + kb*1024 + j*32, bfr[j][0], bfr[j][1]);

      const uint32_t off = (uint32_t)(((2*kb + hi) ^ sw) << 4);
      uint32_t a[2][4];
      #pragma unroll
      for (int mb=0;mb<2;mb++) ldsm4(Abase[mb]+off, a[mb][0],a[mb][1],a[mb][2],a[mb][3]);
      #pragma unroll
      for (int mb=0;mb<2;mb++){
        #pragma unroll
        for (int nb2=0;nb2<4;nb2++){
          mma16816(acc[mb][2*nb2  ], a[mb][0],a[mb][1],a[mb][2],a[mb][3], bfr[2*nb2  ][0], bfr[2*nb2  ][1]);
          mma16816(acc[mb][2*nb2+1], a[mb][0],a[mb][1],a[mb][2],a[mb][3], bfr[2*nb2+1][0], bfr[2*nb2+1][1]);
        }
      }
    }
  }
  __syncthreads();

  // ---- epilogue 1: bias + packed fast gelu -> bf16 G [128 m][256 k] at OFF_A0 ----
  {
    const int rq = lane>>2;
    #pragma unroll
    for (int mb=0;mb<2;mb++){
      const int r0 = wm*32 + mb*16 + rq;
      const int r1 = r0 + 8;
      #pragma unroll
      for (int nb=0;nb<8;nb++){
        const int col = wn*64 + nb*8 + 2*(lane&3);
        float2 bv = *(const float2*)(b3 + col);
        u64 g0 = gelu2(acc[mb][nb][0] + bv.x, acc[mb][nb][1] + bv.y);
        u64 g1 = gelu2(acc[mb][nb][2] + bv.x, acc[mb][nb][3] + bv.y);
        float v0, v1, v2, v3;
        upk2(g0, v0, v1);
        upk2(g1, v2, v3);
        const int chunk = col>>3, wb = (col&7)*2;
        uint32_t o0 = (uint32_t)(r0*512 + ((chunk ^ (r0&7))<<4) + wb);
        uint32_t o1 = (uint32_t)(r1*512 + ((chunk ^ (r1&7))<<4) + wb);
        __nv_bfloat162 h0 = __floats2bfloat162_rn(v0, v1);
        __nv_bfloat162 h1 = __floats2bfloat162_rn(v2, v3);
        *(uint32_t*)(smem + OFF_A0 + o0) = *(uint32_t*)&h0;
        *(uint32_t*)(smem + OFF_A0 + o1) = *(uint32_t*)&h1;
      }
    }
  }
  CP_WAIT(0);                            // w1 tile resident
  __syncthreads();                       // G visible to all warps

  // ---- 1x1 GEMM: D2[128,128] = G[128,256] @ w1T^T (warp tile 32x32) ----
  float a2[2][4][4];
  #pragma unroll
  for (int a=0;a<2;a++)
    #pragma unroll
    for (int b=0;b<4;b++)
      #pragma unroll
      for (int q=0;q<4;q++) a2[a][b][q]=0.f;
  {
    uint32_t Gbase[2], Wbase[2];
    #pragma unroll
    for (int mb=0;mb<2;mb++) Gbase[mb] = sbase + OFF_A0 + (wm*32 + mb*16 + lr)*512;
    #pragma unroll
    for (int nb2=0;nb2<2;nb2++) Wbase[nb2] = sbase + OFF_W + (wn*32 + nb2*16 + lr)*512;

    #pragma unroll
    for (int kb=0; kb<16; kb++){
      const uint32_t off = (uint32_t)(((2*kb + hi) ^ sw) << 4);
      uint32_t a[2][4], bf[2][4];
      #pragma unroll
      for (int mb=0;mb<2;mb++) ldsm4(Gbase[mb]+off, a[mb][0],a[mb][1],a[mb][2],a[mb][3]);
      #pragma unroll
      for (int nb2=0;nb2<2;nb2++) ldsm4(Wbase[nb2]+off, bf[nb2][0],bf[nb2][1],bf[nb2][2],bf[nb2][3]);
      #pragma unroll
      for (int mb=0;mb<2;mb++){
        #pragma unroll
        for (int nb2=0;nb2<2;nb2++){
          mma16816(a2[mb][2*nb2  ], a[mb][0],a[mb][1],a[mb][2],a[mb][3], bf[nb2][0], bf[nb2][2]);
          mma16816(a2[mb][2*nb2+1], a[mb][0],a[mb][1],a[mb][2],a[mb][3], bf[nb2][1], bf[nb2][3]);
        }
      }
    }
  }

  // ---- epilogue 2: bias + residual RMW into g_Y ----
  {
    const int rq = lane>>2;
    #pragma unroll
    for (int mb=0;mb<2;mb++){
      const int r0 = wm*32 + mb*16 + rq;
      float* y0 = g_Y + ((size_t)blockIdx.x*128 + r0)*DDc;
      #pragma unroll
      for (int nb=0;nb<4;nb++){
        const int d = wn*32 + nb*8 + 2*(lane&3);
        float2 bv = *(const float2*)(b1 + d);
        float2 ya = *(float2*)(y0 + d);
        ya.x += a2[mb][nb][0] + bv.x;
        ya.y += a2[mb][nb][1] + bv.y;
        *(float2*)(y0 + d) = ya;
        float2 yb = *(float2*)(y0 + 8*DDc + d);
        yb.x += a2[mb][nb][2] + bv.x;
        yb.y += a2[mb][nb][3] + bv.y;
        *(float2*)(y0 + 8*DDc + d) = yb;
      }
    }
  }
  #undef LOAD_A
}

// ---------------- launch ----------------
extern "C" void kernel_launch(void* const* d_in, const int* in_sizes, int n_in,
                              void* d_out, int out_size){
  const float* X        = (const float*)d_in[0];
  const int*   coords   = (const int*)  d_in[1];
  const float* P        = (const float*)d_in[2];
  const float* ln_scale = (const float*)d_in[3];
  const float* ln_bias  = (const float*)d_in[4];
  const float* w3       = (const float*)d_in[5];
  const float* b3       = (const float*)d_in[6];
  const float* w1       = (const float*)d_in[7];
  const float* b1       = (const float*)d_in[8];
  float* out = (float*)d_out;

  const int SMEM_SZ = 132096 + 1024;
  cudaFuncSetAttribute(k_conv, cudaFuncAttributeMaxDynamicSharedMemorySize, SMEM_SZ);

  // launch order keeps index 3 (ncu's sample slot) = k_conv layer 0
  k_inv    <<<1, 1024>>>(coords);                                   // 0
  k_prep   <<<8576, 256>>>(w3, w1);                                 // 1
  k_fill_ln<<<21632, 256>>>(X, P, ln_scale, ln_bias);               // 2
  k_conv   <<<NTILE, 512, SMEM_SZ>>>(0, b3, b1);                    // 3  <- profiled
  for (int l=1; l<4; l++){
    k_ln  <<<21632, 256>>>(ln_scale + l*DDc, ln_bias + l*DDc);
    k_conv<<<NTILE, 512, SMEM_SZ>>>(l, b3 + l*CHc, b1 + l*DDc);
  }
  k_gather<<<79872, 256>>>(coords, out);
}

// round 13
// speedup vs baseline: 1.0774x; 1.0288x over previous
#include <cuda_runtime.h>
#include <cuda_bf16.h>
#include <stdint.h>
#include <math.h>

#define NBt 256
#define POS 676          // 26*26
#define LLt 624
#define DDc 128
#define CHc 256
#define HP  28           // padded grid 28x28
#define NTILE 1352       // NBt*POS/128 (exact)

typedef unsigned long long u64;

// ---- device-global scratch ----
__device__ float          g_Y  [(size_t)NBt*POS*DDc];      // residual stream, fp32
__device__ __nv_bfloat16  g_Ynp[(size_t)NBt*HP*HP*DDc];    // LN out, bf16, zero-padded
__device__ u64            g_w3F[(size_t)4*9*8*32*32];      // fragment-major conv weights
__device__ __nv_bfloat16  g_w1T[(size_t)4*DDc*CHc];        // [l][d][co]
__device__ int            g_inv[POS];

// ---------------- PTX helpers (baseline PTX only) ----------------
__device__ __forceinline__ uint32_t s2u(const void* p){
  uint32_t a;
  asm("{ .reg .u64 t; cvta.to.shared.u64 t, %1; cvt.u32.u64 %0, t; }" : "=r"(a) : "l"(p));
  return a;
}
#define CP16(dst, src) asm volatile("cp.async.cg.shared.global [%0], [%1], 16;" :: "r"(dst), "l"(src) : "memory")
#define CP_COMMIT()    asm volatile("cp.async.commit_group;" ::: "memory")
#define CP_WAIT(n)     asm volatile("cp.async.wait_group %0;" :: "n"(n) : "memory")

__device__ __forceinline__ void ldsm4(uint32_t addr, uint32_t &r0, uint32_t &r1, uint32_t &r2, uint32_t &r3){
  asm volatile("ldmatrix.sync.aligned.m8n8.x4.shared.b16 {%0,%1,%2,%3}, [%4];"
    : "=r"(r0),"=r"(r1),"=r"(r2),"=r"(r3) : "r"(addr));
}
__device__ __forceinline__ void ldg2(const u64* p, uint32_t &r0, uint32_t &r1){
  asm volatile("ld.global.nc.v2.b32 {%0,%1}, [%2];" : "=r"(r0), "=r"(r1) : "l"(p));
}
__device__ __forceinline__ void mma16816(float* c, uint32_t a0,uint32_t a1,uint32_t a2,uint32_t a3,
                                         uint32_t b0,uint32_t b1){
  asm volatile("mma.sync.aligned.m16n8k16.row.col.f32.bf16.bf16.f32 "
    "{%0,%1,%2,%3}, {%4,%5,%6,%7}, {%8,%9}, {%0,%1,%2,%3};"
    : "+f"(c[0]),"+f"(c[1]),"+f"(c[2]),"+f"(c[3])
    : "r"(a0),"r"(a1),"r"(a2),"r"(a3),"r"(b0),"r"(b1));
}

// ---- packed f32x2 ops ----
__device__ __forceinline__ u64 pk2(float lo, float hi){
  u64 r; asm("mov.b64 %0, {%1, %2};" : "=l"(r) : "f"(lo), "f"(hi)); return r;
}
__device__ __forceinline__ void upk2(u64 v, float &lo, float &hi){
  asm("mov.b64 {%0, %1}, %2;" : "=f"(lo), "=f"(hi) : "l"(v));
}
__device__ __forceinline__ u64 mul2(u64 a, u64 b){
  u64 r; asm("mul.rn.f32x2 %0, %1, %2;" : "=l"(r) : "l"(a), "l"(b)); return r;
}
__device__ __forceinline__ u64 add2(u64 a, u64 b){
  u64 r; asm("add.rn.f32x2 %0, %1, %2;" : "=l"(r) : "l"(a), "l"(b)); return r;
}
__device__ __forceinline__ u64 fma2(u64 a, u64 b, u64 c){
  u64 r; asm("fma.rn.f32x2 %0, %1, %2, %3;" : "=l"(r) : "l"(a), "l"(b), "l"(c)); return r;
}

// branchless MUFU-free packed gelu: 0.5x(1+tanh(x(c0+c1 x^2))), tanh = Pade 7/6
__device__ __forceinline__ u64 gelu2(float v0, float v1){
  const u64 C0  = pk2(0.79788456f, 0.79788456f);
  const u64 C1  = pk2(0.035677408f, 0.035677408f);
  const u64 K378  = pk2(378.f, 378.f);
  const u64 K17325= pk2(17325.f, 17325.f);
  const u64 K135  = pk2(135135.f, 135135.f);
  const u64 K28   = pk2(28.f, 28.f);
  const u64 K3150 = pk2(3150.f, 3150.f);
  const u64 K62370= pk2(62370.f, 62370.f);
  const u64 NONE  = pk2(-1.f, -1.f);
  const u64 HALF  = pk2(0.5f, 0.5f);

  u64 x  = pk2(v0, v1);
  u64 s  = mul2(x, x);
  u64 z  = mul2(x, fma2(C1, s, C0));
  u64 w  = mul2(z, z);
  u64 num = mul2(z, fma2(w, fma2(w, add2(w, K378), K17325), K135));
  u64 den = fma2(w, fma2(w, fma2(w, K28, K3150), K62370), K135);
  float dl, dh; upk2(den, dl, dh);
  float yl = __int_as_float(0x7EF311C3 - __float_as_int(dl));
  float yh = __int_as_float(0x7EF311C3 - __float_as_int(dh));
  u64 y  = pk2(yl, yh);
  u64 nd = mul2(den, NONE);
  y = mul2(y, fma2(nd, y, pk2(2.f,2.f)));
  y = mul2(y, fma2(nd, y, pk2(2.f,2.f)));
  u64 th = mul2(num, y);
  u64 hx = mul2(x, HALF);
  return fma2(th, hx, hx);       // 0.5x + 0.5x*tanh
}

// ---------------- small kernels ----------------
__global__ void k_inv(const int* __restrict__ coords){
  int t = threadIdx.x;
  if (t < POS) g_inv[t] = -1;
  __syncthreads();
  if (t < LLt){
    int r = coords[2*t], c = coords[2*t+1];
    g_inv[r*26 + c] = t;
  }
}

// merged weight prep: blocks [0,1152): w3 fragment pack   [1152,1664): w1T
//                      [1664,8576): g_Ynp border zeroing
__global__ void k_prep(const float* __restrict__ w3, const float* __restrict__ w1){
  int blk = blockIdx.x;
  if (blk < 1152){
    int idx = blk*256 + threadIdx.x;        // [0, 294912)
    int lane = idx & 31;
    int cc   = (idx>>5) & 31;
    int kb   = (idx>>10) & 7;
    int lt   = idx>>13;                     // l*9 + tap, [0,36)
    int n  = cc*8 + (lane>>2);
    int k0 = kb*16 + 2*(lane&3);
    const float* wbase = w3 + (size_t)lt*32768;   // [ci=128][co=256]
    __nv_bfloat162 lo2 = __floats2bfloat162_rn(wbase[(size_t)k0*256 + n],
                                               wbase[(size_t)(k0+1)*256 + n]);
    __nv_bfloat162 hi2 = __floats2bfloat162_rn(wbase[(size_t)(k0+8)*256 + n],
                                               wbase[(size_t)(k0+9)*256 + n]);
    uint32_t u0 = *(uint32_t*)&lo2, u1 = *(uint32_t*)&hi2;
    g_w3F[idx] = ((u64)u1<<32) | (u64)u0;   // v2.b32 load: r0=u0 (b0), r1=u1 (b1)
  } else if (blk < 1664){
    int idx = (blk-1152)*256 + threadIdx.x; // [0, 131072)
    int co = idx & 255;
    int d  = (idx>>8) & 127;
    int l  = idx>>15;
    g_w1T[idx] = __float2bfloat16(w1[((size_t)l*256 + co)*128 + d]);
  } else {
    int idx = (blk-1664)*256 + threadIdx.x; // 256*108*64 entries
    int c2 = idx & 63;
    int j  = (idx >> 6) % 108;
    int b  = (idx >> 6) / 108;
    int r, c;
    if      (j < 28){ r = 0;       c = j; }
    else if (j < 56){ r = 27;      c = j-28; }
    else if (j < 82){ r = j-56+1;  c = 0; }
    else            { r = j-82+1;  c = 27; }
    *(__nv_bfloat162*)(g_Ynp + (((size_t)b*HP + r)*HP + c)*DDc + c2*2) =
        __floats2bfloat162_rn(0.f, 0.f);
  }
}

// fused scatter + layer-0 LN (float4 per lane)
__global__ void k_fill_ln(const float* __restrict__ X, const float* __restrict__ P,
                          const float* __restrict__ scale, const float* __restrict__ bias){
  int cell = blockIdx.x*8 + (threadIdx.x>>5);
  int lane = threadIdx.x & 31;
  int b = cell/POS, sp = cell - b*POS;
  int li = g_inv[sp];
  const float* src = (li >= 0) ? (X + ((size_t)b*LLt + li)*DDc) : P;
  float4 v = ((const float4*)src)[lane];
  ((float4*)(g_Y + (size_t)cell*DDc))[lane] = v;
  float s  = v.x+v.y+v.z+v.w;
  float s2 = v.x*v.x+v.y*v.y+v.z*v.z+v.w*v.w;
  #pragma unroll
  for (int o=16;o;o>>=1){ s += __shfl_xor_sync(~0u,s,o); s2 += __shfl_xor_sync(~0u,s2,o); }
  float mn = s*(1.f/128.f);
  float var = s2*(1.f/128.f) - mn*mn;
  float rs = rsqrtf(var + 1e-5f);
  int h = sp/26, w = sp - h*26;
  __nv_bfloat162* o = (__nv_bfloat162*)(g_Ynp + (((size_t)b*HP + h+1)*HP + (w+1))*DDc);
  float4 sc = ((const float4*)scale)[lane];
  float4 bb = ((const float4*)bias)[lane];
  o[lane*2  ] = __floats2bfloat162_rn((v.x-mn)*rs*sc.x + bb.x, (v.y-mn)*rs*sc.y + bb.y);
  o[lane*2+1] = __floats2bfloat162_rn((v.z-mn)*rs*sc.z + bb.z, (v.w-mn)*rs*sc.w + bb.w);
}

// warp-per-cell LayerNorm (layers 1..3), float4 per lane
__global__ void k_ln(const float* __restrict__ scale, const float* __restrict__ bias){
  int cell = blockIdx.x*8 + (threadIdx.x>>5);
  int lane = threadIdx.x & 31;
  float4 v = ((const float4*)(g_Y + (size_t)cell*DDc))[lane];
  float s  = v.x+v.y+v.z+v.w;
  float s2 = v.x*v.x+v.y*v.y+v.z*v.z+v.w*v.w;
  #pragma unroll
  for (int o=16;o;o>>=1){ s += __shfl_xor_sync(~0u,s,o); s2 += __shfl_xor_sync(~0u,s2,o); }
  float mn = s*(1.f/128.f);
  float var = s2*(1.f/128.f) - mn*mn;
  float rs = rsqrtf(var + 1e-5f);
  int b = cell/POS, sp = cell - b*POS;
  int h = sp/26, w = sp - h*26;
  __nv_bfloat162* o = (__nv_bfloat162*)(g_Ynp + (((size_t)b*HP + h+1)*HP + (w+1))*DDc);
  float4 sc = ((const float4*)scale)[lane];
  float4 bb = ((const float4*)bias)[lane];
  o[lane*2  ] = __floats2bfloat162_rn((v.x-mn)*rs*sc.x + bb.x, (v.y-mn)*rs*sc.y + bb.y);
  o[lane*2+1] = __floats2bfloat162_rn((v.z-mn)*rs*sc.z + bb.z, (v.w-mn)*rs*sc.w + bb.w);
}

// float4 per thread gather (grid must be NBt*LLt*DDc/4/256 = 19968 blocks)
__global__ void k_gather(const int* __restrict__ coords, float* __restrict__ out){
  unsigned idx = blockIdx.x*256u + threadIdx.x;   // 4 floats per thread
  int c4 = idx & 31;
  int l = (idx >> 5) % LLt;
  int b = (idx >> 5) / LLt;
  int r = coords[2*l], cc = coords[2*l+1];
  float4 v = ((const float4*)(g_Y + ((size_t)b*POS + r*26 + cc)*DDc))[c4];
  ((float4*)out)[(size_t)idx] = v;
}

// ---------------- fused conv block: 16 warps; B via PIPELINED fragment LDG ----------------
__global__ void __launch_bounds__(512,1) k_conv(
    int layer, const float* __restrict__ b3, const float* __restrict__ b1)
{
  extern __shared__ unsigned char smraw[];
  uint32_t sb0 = s2u(smraw);
  uint32_t pad = (0u - sb0) & 1023u;
  unsigned char* smem = smraw + pad;
  const uint32_t sbase = sb0 + pad;

  const int tid = threadIdx.x, lane = tid&31, wid = tid>>5;
  const int wm = wid & 3;          // 4-way M split (32 rows each)
  const int wn = wid >> 2;         // 4-way N split (64 cols each)
  const int lr = lane & 15;
  const int hi = lane >> 4;
  const int sw = lane & 7;

  enum { OFF_TAB=0, OFF_A0=1024, OFF_A1=1024+32768,
         OFF_W=1024+65536 };                         // end = 132096

  int* baseT = (int*)(smem + OFF_TAB);
  if (tid < 128){
    int p = blockIdx.x*128 + tid;
    int b = p/POS, sp = p - b*POS;
    int r = sp/26, c = sp - r*26;
    baseT[tid] = ((b*HP + r)*HP + c)*DDc;     // 3x3 window top-left elem offset
  }
  __syncthreads();

  const u64* w3F = g_w3F + (size_t)layer*9*8192 + wn*256 + lane;
  const __nv_bfloat16* w1T = g_w1T + (size_t)layer*DDc*CHc;

  #define LOAD_A(T_, AOFF) do{                                                  \
    const int tapoff = (((T_)/3)*HP + ((T_)%3))*DDc;                             \
    _Pragma("unroll")                                                            \
    for (int it=0; it<4; it++){                                                  \
      int seg = tid + it*512; int m = seg>>4, c = seg&15;                        \
      const __nv_bfloat16* src = g_Ynp + (size_t)(baseT[m] + tapoff) + c*8;      \
      uint32_t dst = sbase + (AOFF) + m*256 + ((c ^ (m&7))<<4);                  \
      CP16(dst, src);                                                            \
    }                                                                            \
  }while(0)

  // B fragment prefetch: bfr[buf][j] for one kb (8 n-chunks of 16)
  uint32_t bfr[2][8][2];
  #define LDB(BUF, T_, KB_) do{                                                 \
    const u64* _p = w3F + (size_t)(T_)*8192 + (KB_)*1024;                        \
    _Pragma("unroll")                                                            \
    for (int j=0;j<8;j++) ldg2(_p + j*32, bfr[BUF][j][0], bfr[BUF][j][1]);       \
  }while(0)

  float acc[2][8][4];
  #pragma unroll
  for (int a=0;a<2;a++)
    #pragma unroll
    for (int b=0;b<8;b++)
      #pragma unroll
      for (int q=0;q<4;q++) acc[a][b][q]=0.f;

  LOAD_A(0, OFF_A0); CP_COMMIT();
  LDB(0, 0, 0);

  for (int t=0; t<9; t++){
    if (t>0) __syncthreads();
    if (t<8){
      if ((t+1)&1) LOAD_A(t+1, OFF_A1);
      else         LOAD_A(t+1, OFF_A0);
      CP_COMMIT();
    } else {
      // prefetch w1 tile [128 d][256 co] into OFF_W
      #pragma unroll
      for (int it=0; it<8; it++){
        int seg = tid + it*512; int row = seg>>5, c = seg&31;
        uint32_t dst = sbase + OFF_W + row*512 + ((c ^ (row&7))<<4);
        CP16(dst, w1T + (size_t)row*CHc + c*8);
      }
      CP_COMMIT();
    }
    CP_WAIT(1);
    __syncthreads();

    const uint32_t abuf = sbase + ((t&1)? OFF_A1 : OFF_A0);
    uint32_t Abase[2];
    #pragma unroll
    for (int mb=0;mb<2;mb++) Abase[mb] = abuf + (wm*32 + mb*16 + lr)*256;

    #pragma unroll
    for (int kb=0; kb<8; kb++){
      const int cur = kb&1;
      // prefetch next kb (or next tap's kb0) while this kb's HMMAs run
      if (kb<7)      LDB(cur^1, t,   kb+1);
      else if (t<8)  LDB(cur^1, t+1, 0);

      const uint32_t off = (uint32_t)(((2*kb + hi) ^ sw) << 4);
      uint32_t a[2][4];
      #pragma unroll
      for (int mb=0;mb<2;mb++) ldsm4(Abase[mb]+off, a[mb][0],a[mb][1],a[mb][2],a[mb][3]);
      #pragma unroll
      for (int mb=0;mb<2;mb++){
        #pragma unroll
        for (int nb2=0;nb2<4;nb2++){
          mma16816(acc[mb][2*nb2  ], a[mb][0],a[mb][1],a[mb][2],a[mb][3], bfr[cur][2*nb2  ][0], bfr[cur][2*nb2  ][1]);
          mma16816(acc[mb][2*nb2+1], a[mb][0],a[mb][1],a[mb][2],a[mb][3], bfr[cur][2*nb2+1][0], bfr[cur][2*nb2+1][1]);
        }
      }
    }
  }
  __syncthreads();

  // ---- epilogue 1: bias + packed fast gelu -> bf16 G [128 m][256 k] at OFF_A0 ----
  {
    const int rq = lane>>2;
    #pragma unroll
    for (int mb=0;mb<2;mb++){
      const int r0 = wm*32 + mb*16 + rq;
      const int r1 = r0 + 8;
      #pragma unroll
      for (int nb=0;nb<8;nb++){
        const int col = wn*64 + nb*8 + 2*(lane&3);
        float2 bv = *(const float2*)(b3 + col);
        u64 g0 = gelu2(acc[mb][nb][0] + bv.x, acc[mb][nb][1] + bv.y);
        u64 g1 = gelu2(acc[mb][nb][2] + bv.x, acc[mb][nb][3] + bv.y);
        float v0, v1, v2, v3;
        upk2(g0, v0, v1);
        upk2(g1, v2, v3);
        const int chunk = col>>3, wb = (col&7)*2;
        uint32_t o0 = (uint32_t)(r0*512 + ((chunk ^ (r0&7))<<4) + wb);
        uint32_t o1 = (uint32_t)(r1*512 + ((chunk ^ (r1&7))<<4) + wb);
        __nv_bfloat162 h0 = __floats2bfloat162_rn(v0, v1);
        __nv_bfloat162 h1 = __floats2bfloat162_rn(v2, v3);
        *(uint32_t*)(smem + OFF_A0 + o0) = *(uint32_t*)&h0;
        *(uint32_t*)(smem + OFF_A0 + o1) = *(uint32_t*)&h1;
      }
    }
  }
  CP_WAIT(0);                            // w1 tile resident
  __syncthreads();                       // G visible to all warps

  // ---- 1x1 GEMM: D2[128,128] = G[128,256] @ w1T^T (warp tile 32x32) ----
  float a2[2][4][4];
  #pragma unroll
  for (int a=0;a<2;a++)
    #pragma unroll
    for (int b=0;b<4;b++)
      #pragma unroll
      for (int q=0;q<4;q++) a2[a][b][q]=0.f;
  {
    uint32_t Gbase[2], Wbase[2];
    #pragma unroll
    for (int mb=0;mb<2;mb++) Gbase[mb] = sbase + OFF_A0 + (wm*32 + mb*16 + lr)*512;
    #pragma unroll
    for (int nb2=0;nb2<2;nb2++) Wbase[nb2] = sbase + OFF_W + (wn*32 + nb2*16 + lr)*512;

    #pragma unroll
    for (int kb=0; kb<16; kb++){
      const uint32_t off = (uint32_t)(((2*kb + hi) ^ sw) << 4);
      uint32_t a[2][4], bf[2][4];
      #pragma unroll
      for (int mb=0;mb<2;mb++) ldsm4(Gbase[mb]+off, a[mb][0],a[mb][1],a[mb][2],a[mb][3]);
      #pragma unroll
      for (int nb2=0;nb2<2;nb2++) ldsm4(Wbase[nb2]+off, bf[nb2][0],bf[nb2][1],bf[nb2][2],bf[nb2][3]);
      #pragma unroll
      for (int mb=0;mb<2;mb++){
        #pragma unroll
        for (int nb2=0;nb2<2;nb2++){
          mma16816(a2[mb][2*nb2  ], a[mb][0],a[mb][1],a[mb][2],a[mb][3], bf[nb2][0], bf[nb2][2]);
          mma16816(a2[mb][2*nb2+1], a[mb][0],a[mb][1],a[mb][2],a[mb][3], bf[nb2][1], bf[nb2][3]);
        }
      }
    }
  }

  // ---- epilogue 2: bias + residual RMW into g_Y ----
  {
    const int rq = lane>>2;
    #pragma unroll
    for (int mb=0;mb<2;mb++){
      const int r0 = wm*32 + mb*16 + rq;
      float* y0 = g_Y + ((size_t)blockIdx.x*128 + r0)*DDc;
      #pragma unroll
      for (int nb=0;nb<4;nb++){
        const int d = wn*32 + nb*8 + 2*(lane&3);
        float2 bv = *(const float2*)(b1 + d);
        float2 ya = *(float2*)(y0 + d);
        ya.x += a2[mb][nb][0] + bv.x;
        ya.y += a2[mb][nb][1] + bv.y;
        *(float2*)(y0 + d) = ya;
        float2 yb = *(float2*)(y0 + 8*DDc + d);
        yb.x += a2[mb][nb][2] + bv.x;
        yb.y += a2[mb][nb][3] + bv.y;
        *(float2*)(y0 + 8*DDc + d) = yb;
      }
    }
  }
  #undef LOAD_A
  #undef LDB
}

// ---------------- launch ----------------
extern "C" void kernel_launch(void* const* d_in, const int* in_sizes, int n_in,
                              void* d_out, int out_size){
  const float* X        = (const float*)d_in[0];
  const int*   coords   = (const int*)  d_in[1];
  const float* P        = (const float*)d_in[2];
  const float* ln_scale = (const float*)d_in[3];
  const float* ln_bias  = (const float*)d_in[4];
  const float* w3       = (const float*)d_in[5];
  const float* b3       = (const float*)d_in[6];
  const float* w1       = (const float*)d_in[7];
  const float* b1       = (const float*)d_in[8];
  float* out = (float*)d_out;

  const int SMEM_SZ = 132096 + 1024;
  cudaFuncSetAttribute(k_conv, cudaFuncAttributeMaxDynamicSharedMemorySize, SMEM_SZ);

  // launch order keeps index 3 (ncu's sample slot) = k_conv layer 0
  k_inv    <<<1, 1024>>>(coords);                                   // 0
  k_prep   <<<8576, 256>>>(w3, w1);                                 // 1
  k_fill_ln<<<21632, 256>>>(X, P, ln_scale, ln_bias);               // 2
  k_conv   <<<NTILE, 512, SMEM_SZ>>>(0, b3, b1);                    // 3  <- profiled
  for (int l=1; l<4; l++){
    k_ln  <<<21632, 256>>>(ln_scale + l*DDc, ln_bias + l*DDc);
    k_conv<<<NTILE, 512, SMEM_SZ>>>(l, b3 + l*CHc, b1 + l*DDc);
  }
  k_gather<<<19968, 256>>>(coords, out);   // 20,447,232 floats / 4 / 256
}

// round 15
// speedup vs baseline: 1.0996x; 1.0206x over previous
#include <cuda_runtime.h>
#include <cuda_bf16.h>
#include <stdint.h>
#include <math.h>

#define NBt 256
#define POS 676          // 26*26
#define LLt 624
#define DDc 128
#define CHc 256
#define HP  28           // padded grid 28x28
#define NTILE 1352       // NBt*POS/128 (exact)
#define NPSZ ((size_t)NBt*HP*HP*DDc)   // one padded-grid buffer

typedef unsigned long long u64;

// ---- device-global scratch ----
__device__ float          g_Y  [(size_t)NBt*POS*DDc];      // residual stream, fp32
__device__ __nv_bfloat16  g_Ynp[2*NPSZ];                   // LN out, bf16, DOUBLE-BUFFERED
__device__ u64            g_w3F[(size_t)4*9*8*32*32];      // fragment-major conv weights
__device__ __nv_bfloat16  g_w1T[(size_t)4*DDc*CHc];        // [l][d][co]
__device__ int            g_inv[POS];

// ---------------- PTX helpers (baseline PTX only) ----------------
__device__ __forceinline__ uint32_t s2u(const void* p){
  uint32_t a;
  asm("{ .reg .u64 t; cvta.to.shared.u64 t, %1; cvt.u32.u64 %0, t; }" : "=r"(a) : "l"(p));
  return a;
}
#define CP16(dst, src) asm volatile("cp.async.cg.shared.global [%0], [%1], 16;" :: "r"(dst), "l"(src) : "memory")
#define CP_COMMIT()    asm volatile("cp.async.commit_group;" ::: "memory")
#define CP_WAIT(n)     asm volatile("cp.async.wait_group %0;" :: "n"(n) : "memory")

__device__ __forceinline__ void ldsm4(uint32_t addr, uint32_t &r0, uint32_t &r1, uint32_t &r2, uint32_t &r3){
  asm volatile("ldmatrix.sync.aligned.m8n8.x4.shared.b16 {%0,%1,%2,%3}, [%4];"
    : "=r"(r0),"=r"(r1),"=r"(r2),"=r"(r3) : "r"(addr));
}
__device__ __forceinline__ void ldg2(const u64* p, uint32_t &r0, uint32_t &r1){
  asm volatile("ld.global.nc.v2.b32 {%0,%1}, [%2];" : "=r"(r0), "=r"(r1) : "l"(p));
}
__device__ __forceinline__ void mma16816(float* c, uint32_t a0,uint32_t a1,uint32_t a2,uint32_t a3,
                                         uint32_t b0,uint32_t b1){
  asm volatile("mma.sync.aligned.m16n8k16.row.col.f32.bf16.bf16.f32 "
    "{%0,%1,%2,%3}, {%4,%5,%6,%7}, {%8,%9}, {%0,%1,%2,%3};"
    : "+f"(c[0]),"+f"(c[1]),"+f"(c[2]),"+f"(c[3])
    : "r"(a0),"r"(a1),"r"(a2),"r"(a3),"r"(b0),"r"(b1));
}

// ---- packed f32x2 ops ----
__device__ __forceinline__ u64 pk2(float lo, float hi){
  u64 r; asm("mov.b64 %0, {%1, %2};" : "=l"(r) : "f"(lo), "f"(hi)); return r;
}
__device__ __forceinline__ void upk2(u64 v, float &lo, float &hi){
  asm("mov.b64 {%0, %1}, %2;" : "=f"(lo), "=f"(hi) : "l"(v));
}
__device__ __forceinline__ u64 mul2(u64 a, u64 b){
  u64 r; asm("mul.rn.f32x2 %0, %1, %2;" : "=l"(r) : "l"(a), "l"(b)); return r;
}
__device__ __forceinline__ u64 add2(u64 a, u64 b){
  u64 r; asm("add.rn.f32x2 %0, %1, %2;" : "=l"(r) : "l"(a), "l"(b)); return r;
}
__device__ __forceinline__ u64 fma2(u64 a, u64 b, u64 c){
  u64 r; asm("fma.rn.f32x2 %0, %1, %2, %3;" : "=l"(r) : "l"(a), "l"(b), "l"(c)); return r;
}

// branchless MUFU-free packed gelu: 0.5x(1+tanh(x(c0+c1 x^2))), tanh = Pade 7/6
__device__ __forceinline__ u64 gelu2(float v0, float v1){
  const u64 C0  = pk2(0.79788456f, 0.79788456f);
  const u64 C1  = pk2(0.035677408f, 0.035677408f);
  const u64 K378  = pk2(378.f, 378.f);
  const u64 K17325= pk2(17325.f, 17325.f);
  const u64 K135  = pk2(135135.f, 135135.f);
  const u64 K28   = pk2(28.f, 28.f);
  const u64 K3150 = pk2(3150.f, 3150.f);
  const u64 K62370= pk2(62370.f, 62370.f);
  const u64 NONE  = pk2(-1.f, -1.f);
  const u64 HALF  = pk2(0.5f, 0.5f);

  u64 x  = pk2(v0, v1);
  u64 s  = mul2(x, x);
  u64 z  = mul2(x, fma2(C1, s, C0));
  u64 w  = mul2(z, z);
  u64 num = mul2(z, fma2(w, fma2(w, add2(w, K378), K17325), K135));
  u64 den = fma2(w, fma2(w, fma2(w, K28, K3150), K62370), K135);
  float dl, dh; upk2(den, dl, dh);
  float yl = __int_as_float(0x7EF311C3 - __float_as_int(dl));
  float yh = __int_as_float(0x7EF311C3 - __float_as_int(dh));
  u64 y  = pk2(yl, yh);
  u64 nd = mul2(den, NONE);
  y = mul2(y, fma2(nd, y, pk2(2.f,2.f)));
  y = mul2(y, fma2(nd, y, pk2(2.f,2.f)));
  u64 th = mul2(num, y);
  u64 hx = mul2(x, HALF);
  return fma2(th, hx, hx);       // 0.5x + 0.5x*tanh
}

// ---------------- small kernels ----------------
__global__ void k_inv(const int* __restrict__ coords){
  int t = threadIdx.x;
  if (t < POS) g_inv[t] = -1;
  __syncthreads();
  if (t < LLt){
    int r = coords[2*t], c = coords[2*t+1];
    g_inv[r*26 + c] = t;
  }
}

// merged weight prep: blocks [0,1152): w3 fragment pack   [1152,1664): w1T
//                      [1664,8576): g_Ynp border zeroing (BOTH buffers)
__global__ void k_prep(const float* __restrict__ w3, const float* __restrict__ w1){
  int blk = blockIdx.x;
  if (blk < 1152){
    int idx = blk*256 + threadIdx.x;        // [0, 294912)
    int lane = idx & 31;
    int cc   = (idx>>5) & 31;
    int kb   = (idx>>10) & 7;
    int lt   = idx>>13;                     // l*9 + tap, [0,36)
    int n  = cc*8 + (lane>>2);
    int k0 = kb*16 + 2*(lane&3);
    const float* wbase = w3 + (size_t)lt*32768;   // [ci=128][co=256]
    __nv_bfloat162 lo2 = __floats2bfloat162_rn(wbase[(size_t)k0*256 + n],
                                               wbase[(size_t)(k0+1)*256 + n]);
    __nv_bfloat162 hi2 = __floats2bfloat162_rn(wbase[(size_t)(k0+8)*256 + n],
                                               wbase[(size_t)(k0+9)*256 + n]);
    uint32_t u0 = *(uint32_t*)&lo2, u1 = *(uint32_t*)&hi2;
    g_w3F[idx] = ((u64)u1<<32) | (u64)u0;   // v2.b32 load: r0=u0 (b0), r1=u1 (b1)
  } else if (blk < 1664){
    int idx = (blk-1152)*256 + threadIdx.x; // [0, 131072)
    int co = idx & 255;
    int d  = (idx>>8) & 127;
    int l  = idx>>15;
    g_w1T[idx] = __float2bfloat16(w1[((size_t)l*256 + co)*128 + d]);
  } else {
    int idx = (blk-1664)*256 + threadIdx.x; // 256*108*64 entries
    int c2 = idx & 63;
    int j  = (idx >> 6) % 108;
    int b  = (idx >> 6) / 108;
    int r, c;
    if      (j < 28){ r = 0;       c = j; }
    else if (j < 56){ r = 27;      c = j-28; }
    else if (j < 82){ r = j-56+1;  c = 0; }
    else            { r = j-82+1;  c = 27; }
    size_t off = (((size_t)b*HP + r)*HP + c)*DDc + c2*2;
    __nv_bfloat162 z2 = __floats2bfloat162_rn(0.f, 0.f);
    *(__nv_bfloat162*)(g_Ynp + off)        = z2;
    *(__nv_bfloat162*)(g_Ynp + NPSZ + off) = z2;
  }
}

// fused scatter + layer-0 LN (float4 per lane) -> buffer 0
__global__ void k_fill_ln(const float* __restrict__ X, const float* __restrict__ P,
                          const float* __restrict__ scale, const float* __restrict__ bias){
  int cell = blockIdx.x*8 + (threadIdx.x>>5);
  int lane = threadIdx.x & 31;
  int b = cell/POS, sp = cell - b*POS;
  int li = g_inv[sp];
  const float* src = (li >= 0) ? (X + ((size_t)b*LLt + li)*DDc) : P;
  float4 v = ((const float4*)src)[lane];
  ((float4*)(g_Y + (size_t)cell*DDc))[lane] = v;
  float s  = v.x+v.y+v.z+v.w;
  float s2 = v.x*v.x+v.y*v.y+v.z*v.z+v.w*v.w;
  #pragma unroll
  for (int o=16;o;o>>=1){ s += __shfl_xor_sync(~0u,s,o); s2 += __shfl_xor_sync(~0u,s2,o); }
  float mn = s*(1.f/128.f);
  float var = s2*(1.f/128.f) - mn*mn;
  float rs = rsqrtf(var + 1e-5f);
  int h = sp/26, w = sp - h*26;
  __nv_bfloat162* o = (__nv_bfloat162*)(g_Ynp + (((size_t)b*HP + h+1)*HP + (w+1))*DDc);
  float4 sc = ((const float4*)scale)[lane];
  float4 bb = ((const float4*)bias)[lane];
  o[lane*2  ] = __floats2bfloat162_rn((v.x-mn)*rs*sc.x + bb.x, (v.y-mn)*rs*sc.y + bb.y);
  o[lane*2+1] = __floats2bfloat162_rn((v.z-mn)*rs*sc.z + bb.z, (v.w-mn)*rs*sc.w + bb.w);
}

// float4 per thread gather (grid must be NBt*LLt*DDc/4/256 = 19968 blocks)
__global__ void k_gather(const int* __restrict__ coords, float* __restrict__ out){
  unsigned idx = blockIdx.x*256u + threadIdx.x;   // 4 floats per thread
  int c4 = idx & 31;
  int l = (idx >> 5) % LLt;
  int b = (idx >> 5) / LLt;
  int r = coords[2*l], cc = coords[2*l+1];
  float4 v = ((const float4*)(g_Y + ((size_t)b*POS + r*26 + cc)*DDc))[c4];
  ((float4*)out)[(size_t)idx] = v;
}

// ---------------- fused conv block: 16 warps; pipelined B-LDG; fused next-layer LN ----------------
// Reads ynp_in (this layer's LN grid), writes ynp_out (next layer's) — ping-pong, race-free.
__global__ void __launch_bounds__(512,1) k_conv(
    int layer, const float* __restrict__ b3, const float* __restrict__ b1,
    const float* __restrict__ lns, const float* __restrict__ lnb, int do_ln,
    const __nv_bfloat16* __restrict__ ynp_in, __nv_bfloat16* __restrict__ ynp_out)
{
  extern __shared__ unsigned char smraw[];
  uint32_t sb0 = s2u(smraw);
  uint32_t pad = (0u - sb0) & 1023u;
  unsigned char* smem = smraw + pad;
  const uint32_t sbase = sb0 + pad;

  const int tid = threadIdx.x, lane = tid&31, wid = tid>>5;
  const int wm = wid & 3;          // 4-way M split (32 rows each)
  const int wn = wid >> 2;         // 4-way N split (64 cols each)
  const int lr = lane & 15;
  const int hi = lane >> 4;
  const int sw = lane & 7;

  enum { OFF_TAB=0, OFF_A0=1024, OFF_A1=1024+32768,
         OFF_W=1024+65536 };                         // end = 132096
  // after the 1x1 GEMM, OFF_A0..+64KB is reused as the fp32 Y-row buffer (YS)

  int* baseT = (int*)(smem + OFF_TAB);
  if (tid < 128){
    int p = blockIdx.x*128 + tid;
    int b = p/POS, sp = p - b*POS;
    int r = sp/26, c = sp - r*26;
    baseT[tid] = ((b*HP + r)*HP + c)*DDc;     // 3x3 window top-left elem offset
  }
  __syncthreads();

  const u64* w3F = g_w3F + (size_t)layer*9*8192 + wn*256 + lane;
  const __nv_bfloat16* w1T = g_w1T + (size_t)layer*DDc*CHc;

  #define LOAD_A(T_, AOFF) do{                                                  \
    const int tapoff = (((T_)/3)*HP + ((T_)%3))*DDc;                             \
    _Pragma("unroll")                                                            \
    for (int it=0; it<4; it++){                                                  \
      int seg = tid + it*512; int m = seg>>4, c = seg&15;                        \
      const __nv_bfloat16* src = ynp_in + (size_t)(baseT[m] + tapoff) + c*8;     \
      uint32_t dst = sbase + (AOFF) + m*256 + ((c ^ (m&7))<<4);                  \
      CP16(dst, src);                                                            \
    }                                                                            \
  }while(0)

  uint32_t bfr[2][8][2];
  #define LDB(BUF, T_, KB_) do{                                                 \
    const u64* _p = w3F + (size_t)(T_)*8192 + (KB_)*1024;                        \
    _Pragma("unroll")                                                            \
    for (int j=0;j<8;j++) ldg2(_p + j*32, bfr[BUF][j][0], bfr[BUF][j][1]);       \
  }while(0)

  float acc[2][8][4];
  #pragma unroll
  for (int a=0;a<2;a++)
    #pragma unroll
    for (int b=0;b<8;b++)
      #pragma unroll
      for (int q=0;q<4;q++) acc[a][b][q]=0.f;

  LOAD_A(0, OFF_A0); CP_COMMIT();
  LDB(0, 0, 0);

  for (int t=0; t<9; t++){
    if (t>0) __syncthreads();
    if (t<8){
      if ((t+1)&1) LOAD_A(t+1, OFF_A1);
      else         LOAD_A(t+1, OFF_A0);
      CP_COMMIT();
    } else {
      // prefetch w1 tile [128 d][256 co] into OFF_W
      #pragma unroll
      for (int it=0; it<8; it++){
        int seg = tid + it*512; int row = seg>>5, c = seg&31;
        uint32_t dst = sbase + OFF_W + row*512 + ((c ^ (row&7))<<4);
        CP16(dst, w1T + (size_t)row*CHc + c*8);
      }
      CP_COMMIT();
    }
    CP_WAIT(1);
    __syncthreads();

    const uint32_t abuf = sbase + ((t&1)? OFF_A1 : OFF_A0);
    uint32_t Abase[2];
    #pragma unroll
    for (int mb=0;mb<2;mb++) Abase[mb] = abuf + (wm*32 + mb*16 + lr)*256;

    #pragma unroll
    for (int kb=0; kb<8; kb++){
      const int cur = kb&1;
      if (kb<7)      LDB(cur^1, t,   kb+1);
      else if (t<8)  LDB(cur^1, t+1, 0);

      const uint32_t off = (uint32_t)(((2*kb + hi) ^ sw) << 4);
      uint32_t a[2][4];
      #pragma unroll
      for (int mb=0;mb<2;mb++) ldsm4(Abase[mb]+off, a[mb][0],a[mb][1],a[mb][2],a[mb][3]);
      #pragma unroll
      for (int mb=0;mb<2;mb++){
        #pragma unroll
        for (int nb2=0;nb2<4;nb2++){
          mma16816(acc[mb][2*nb2  ], a[mb][0],a[mb][1],a[mb][2],a[mb][3], bfr[cur][2*nb2  ][0], bfr[cur][2*nb2  ][1]);
          mma16816(acc[mb][2*nb2+1], a[mb][0],a[mb][1],a[mb][2],a[mb][3], bfr[cur][2*nb2+1][0], bfr[cur][2*nb2+1][1]);
        }
      }
    }
  }
  __syncthreads();

  // ---- epilogue 1: bias + packed fast gelu -> bf16 G [128 m][256 k] at OFF_A0 ----
  {
    const int rq = lane>>2;
    #pragma unroll
    for (int mb=0;mb<2;mb++){
      const int r0 = wm*32 + mb*16 + rq;
      const int r1 = r0 + 8;
      #pragma unroll
      for (int nb=0;nb<8;nb++){
        const int col = wn*64 + nb*8 + 2*(lane&3);
        float2 bv = *(const float2*)(b3 + col);
        u64 g0 = gelu2(acc[mb][nb][0] + bv.x, acc[mb][nb][1] + bv.y);
        u64 g1 = gelu2(acc[mb][nb][2] + bv.x, acc[mb][nb][3] + bv.y);
        float v0, v1, v2, v3;
        upk2(g0, v0, v1);
        upk2(g1, v2, v3);
        const int chunk = col>>3, wb = (col&7)*2;
        uint32_t o0 = (uint32_t)(r0*512 + ((chunk ^ (r0&7))<<4) + wb);
        uint32_t o1 = (uint32_t)(r1*512 + ((chunk ^ (r1&7))<<4) + wb);
        __nv_bfloat162 h0 = __floats2bfloat162_rn(v0, v1);
        __nv_bfloat162 h1 = __floats2bfloat162_rn(v2, v3);
        *(uint32_t*)(smem + OFF_A0 + o0) = *(uint32_t*)&h0;
        *(uint32_t*)(smem + OFF_A0 + o1) = *(uint32_t*)&h1;
      }
    }
  }
  CP_WAIT(0);                            // w1 tile resident
  __syncthreads();                       // G visible to all warps

  // ---- 1x1 GEMM: D2[128,128] = G[128,256] @ w1T^T (warp tile 32x32) ----
  float a2[2][4][4];
  #pragma unroll
  for (int a=0;a<2;a++)
    #pragma unroll
    for (int b=0;b<4;b++)
      #pragma unroll
      for (int q=0;q<4;q++) a2[a][b][q]=0.f;
  {
    uint32_t Gbase[2], Wbase[2];
    #pragma unroll
    for (int mb=0;mb<2;mb++) Gbase[mb] = sbase + OFF_A0 + (wm*32 + mb*16 + lr)*512;
    #pragma unroll
    for (int nb2=0;nb2<2;nb2++) Wbase[nb2] = sbase + OFF_W + (wn*32 + nb2*16 + lr)*512;

    #pragma unroll
    for (int kb=0; kb<16; kb++){
      const uint32_t off = (uint32_t)(((2*kb + hi) ^ sw) << 4);
      uint32_t a[2][4], bf[2][4];
      #pragma unroll
      for (int mb=0;mb<2;mb++) ldsm4(Gbase[mb]+off, a[mb][0],a[mb][1],a[mb][2],a[mb][3]);
      #pragma unroll
      for (int nb2=0;nb2<2;nb2++) ldsm4(Wbase[nb2]+off, bf[nb2][0],bf[nb2][1],bf[nb2][2],bf[nb2][3]);
      #pragma unroll
      for (int mb=0;mb<2;mb++){
        #pragma unroll
        for (int nb2=0;nb2<2;nb2++){
          mma16816(a2[mb][2*nb2  ], a[mb][0],a[mb][1],a[mb][2],a[mb][3], bf[nb2][0], bf[nb2][2]);
          mma16816(a2[mb][2*nb2+1], a[mb][0],a[mb][1],a[mb][2],a[mb][3], bf[nb2][1], bf[nb2][3]);
        }
      }
    }
  }
  if (do_ln) __syncthreads();            // all warps done reading G before YS overwrite

  // ---- epilogue 2: bias + residual RMW into g_Y (+ stage rows into smem YS) ----
  {
    const int rq = lane>>2;
    #pragma unroll
    for (int mb=0;mb<2;mb++){
      const int r0 = wm*32 + mb*16 + rq;
      float* y0 = g_Y + ((size_t)blockIdx.x*128 + r0)*DDc;
      #pragma unroll
      for (int nb=0;nb<4;nb++){
        const int d = wn*32 + nb*8 + 2*(lane&3);
        float2 bv = *(const float2*)(b1 + d);
        float2 ya = *(float2*)(y0 + d);
        ya.x += a2[mb][nb][0] + bv.x;
        ya.y += a2[mb][nb][1] + bv.y;
        *(float2*)(y0 + d) = ya;
        float2 yb = *(float2*)(y0 + 8*DDc + d);
        yb.x += a2[mb][nb][2] + bv.x;
        yb.y += a2[mb][nb][3] + bv.y;
        *(float2*)(y0 + 8*DDc + d) = yb;
        if (do_ln){
          const int r1 = r0 + 8;
          const uint32_t ch = (uint32_t)(d>>3);
          const uint32_t ob = (uint32_t)((d&7)*4);
          *(float2*)(smem + OFF_A0 + r0*512 + ((ch ^ (uint32_t)(r0&7))<<5) + ob) = ya;
          *(float2*)(smem + OFF_A0 + r1*512 + ((ch ^ (uint32_t)(r1&7))<<5) + ob) = yb;
        }
      }
    }
  }

  // ---- epilogue 3: fused next-layer LN, warp-per-row, coalesced writes -> ynp_out ----
  if (do_ln){
    __syncthreads();
    float4 sc = ((const float4*)lns)[lane];
    float4 bb = ((const float4*)lnb)[lane];
    #pragma unroll
    for (int rr=0; rr<8; rr++){
      const int row = wid*8 + rr;
      float4 v = *(float4*)(smem + OFF_A0 + row*512 +
                            (((uint32_t)(lane>>1) ^ (uint32_t)(row&7))<<5) + (lane&1)*16);
      float s  = v.x+v.y+v.z+v.w;
      float s2 = v.x*v.x+v.y*v.y+v.z*v.z+v.w*v.w;
      #pragma unroll
      for (int o=16;o;o>>=1){ s += __shfl_xor_sync(~0u,s,o); s2 += __shfl_xor_sync(~0u,s2,o); }
      float mn = s*(1.f/128.f);
      float var = s2*(1.f/128.f) - mn*mn;
      float rs = rsqrtf(var + 1e-5f);
      __nv_bfloat162* o2 = (__nv_bfloat162*)(ynp_out + (size_t)baseT[row] + 29*DDc);
      o2[lane*2  ] = __floats2bfloat162_rn((v.x-mn)*rs*sc.x + bb.x, (v.y-mn)*rs*sc.y + bb.y);
      o2[lane*2+1] = __floats2bfloat162_rn((v.z-mn)*rs*sc.z + bb.z, (v.w-mn)*rs*sc.w + bb.w);
    }
  }
  #undef LOAD_A
  #undef LDB
}

// ---------------- launch ----------------
extern "C" void kernel_launch(void* const* d_in, const int* in_sizes, int n_in,
                              void* d_out, int out_size){
  const float* X        = (const float*)d_in[0];
  const int*   coords   = (const int*)  d_in[1];
  const float* P        = (const float*)d_in[2];
  const float* ln_scale = (const float*)d_in[3];
  const float* ln_bias  = (const float*)d_in[4];
  const float* w3       = (const float*)d_in[5];
  const float* b3       = (const float*)d_in[6];
  const float* w1       = (const float*)d_in[7];
  const float* b1       = (const float*)d_in[8];
  float* out = (float*)d_out;

  const int SMEM_SZ = 132096 + 1024;
  cudaFuncSetAttribute(k_conv, cudaFuncAttributeMaxDynamicSharedMemorySize, SMEM_SZ);

  __nv_bfloat16* ynp = 0; cudaGetSymbolAddress((void**)&ynp, g_Ynp);

  // launch order keeps index 3 (ncu's sample slot) = k_conv layer 0
  k_inv    <<<1, 1024>>>(coords);                                   // 0
  k_prep   <<<8576, 256>>>(w3, w1);                                 // 1
  k_fill_ln<<<21632, 256>>>(X, P, ln_scale, ln_bias);               // 2 -> buf 0
  for (int l=0; l<4; l++){
    int nl = (l<3) ? (l+1) : 3;
    const __nv_bfloat16* in  = ynp + (size_t)(l&1)*NPSZ;
    __nv_bfloat16*       outp= ynp + (size_t)((l+1)&1)*NPSZ;
    k_conv<<<NTILE, 512, SMEM_SZ>>>(l, b3 + l*CHc, b1 + l*DDc,
                                    ln_scale + nl*DDc, ln_bias + nl*DDc,
                                    (l<3)?1:0, in, outp);
  }
  k_gather<<<19968, 256>>>(coords, out);   // 20,447,232 floats / 4 / 256
}